// round 10
// baseline (speedup 1.0000x reference)
#include <cuda_runtime.h>
#include <cuda_bf16.h>
#include <cuda_fp16.h>
#include <cstdint>

// ---------------------------------------------------------------------------
// image_prj: D = dct2(image) [2048x2048, ortho] -> pad to 2198x2198 ->
// 32-angle radon (bilinear, WRAP) -> lines^T / max
// GEMMs: mma.sync bf16x3 split.  Pad image stored as fp16 (values are
// orthonormal-DCT of N(0,1) -> O(5), fp16-safe).  Radon: 16B cp.async
// footprint staging (half traffic) + convert-free bilinear.
// ---------------------------------------------------------------------------

#define MM    2048
#define PP    2198
#define PPS   2200               // padded row stride in halves (16B-aligned rows)
#define PADB  75
#define NANG  32
#define TOT   (NANG * PP)
#define NYT   35
#define NXT   35

__device__ __nv_bfloat16 g_Ch[MM * MM], g_Cl[MM * MM];
__device__ __nv_bfloat16 g_XTh[MM * MM], g_XTl[MM * MM];
__device__ __nv_bfloat16 g_Th[MM * MM], g_Tl[MM * MM];
__device__ __half   g_pad[PP * PPS];
__device__ float    g_lpart[NYT * TOT];
__device__ float    g_lines[TOT];
__device__ unsigned g_maxbits;

// ------------------------------ PTX helpers -------------------------------
__device__ __forceinline__ uint32_t smem_u32(const void* p) {
    uint32_t a;
    asm("{ .reg .u64 t; cvta.to.shared.u64 t, %1; cvt.u32.u64 %0, t; }"
        : "=r"(a) : "l"(p));
    return a;
}
#define CP_COMMIT() asm volatile("cp.async.commit_group;" ::: "memory")
#define CP_WAIT(n)  asm volatile("cp.async.wait_group %0;" :: "n"(n) : "memory")

__device__ __forceinline__ void cp16(uint32_t dst, const void* src) {
    asm volatile("cp.async.cg.shared.global [%0], [%1], 16;"
                 :: "r"(dst), "l"(src) : "memory");
}
__device__ __forceinline__ void ldsm4(uint32_t& r0, uint32_t& r1,
                                      uint32_t& r2, uint32_t& r3, uint32_t a) {
    asm volatile("ldmatrix.sync.aligned.m8n8.x4.shared.b16 {%0,%1,%2,%3}, [%4];"
                 : "=r"(r0), "=r"(r1), "=r"(r2), "=r"(r3) : "r"(a));
}
__device__ __forceinline__ void mma16816(float* d, const uint32_t* a,
                                         const uint32_t* b) {
    asm volatile("mma.sync.aligned.m16n8k16.row.col.f32.bf16.bf16.f32 "
                 "{%0,%1,%2,%3}, {%4,%5,%6,%7}, {%8,%9}, {%0,%1,%2,%3};"
                 : "+f"(d[0]), "+f"(d[1]), "+f"(d[2]), "+f"(d[3])
                 : "r"(a[0]), "r"(a[1]), "r"(a[2]), "r"(a[3]),
                   "r"(b[0]), "r"(b[1]));
}
__device__ __forceinline__ uint32_t sw128(uint32_t b) { return b ^ ((b >> 3) & 0x70); }

// --------------------------- small prep kernels ---------------------------
#define NB1 (150 * PP)
#define NB2 (MM * 150)
__global__ void init_border_kernel() {
    int idx = blockIdx.x * 256 + threadIdx.x;
    if (idx == 0) g_maxbits = 0u;
    if (idx < NB1) {
        int r = idx / PP, c = idx % PP;
        int row = (r < 75) ? r : (2123 + r - 75);
        g_pad[(size_t)row * PPS + c] = __float2half(0.0f);
    } else if (idx < NB1 + NB2) {
        int j = idx - NB1;
        int r = j / 150, c = j % 150;
        int col = (c < 75) ? c : (2123 + c - 75);
        g_pad[(size_t)(75 + r) * PPS + col] = __float2half(0.0f);
    }
}

__global__ void gen_dct_kernel() {
    int idx = blockIdx.x * 256 + threadIdx.x;
    if (idx >= MM * MM) return;
    int k = idx >> 11;
    int n = idx & (MM - 1);
    int r = ((2 * n + 1) * k) & (4 * MM - 1);
    float t = (float)r * (1.0f / (2.0f * MM));
    float c = cospif(t);
    float s = (k == 0) ? 0.022097086912079608f : 0.03125f;
    float v = s * c;
    __nv_bfloat16 h = __float2bfloat16(v);
    g_Ch[idx] = h;
    g_Cl[idx] = __float2bfloat16(v - __bfloat162float(h));
}

__global__ void transpose_split_kernel(const float* __restrict__ img) {
    __shared__ float tile[32][33];
    int bx = blockIdx.x * 32, by = blockIdx.y * 32;
    int tx = threadIdx.x, ty = threadIdx.y;
#pragma unroll
    for (int i = 0; i < 4; i++)
        tile[ty + i * 8][tx] = img[(size_t)(by + ty + i * 8) * MM + bx + tx];
    __syncthreads();
#pragma unroll
    for (int i = 0; i < 4; i++) {
        float v = tile[tx][ty + i * 8];
        __nv_bfloat16 h = __float2bfloat16(v);
        size_t o = (size_t)(bx + ty + i * 8) * MM + by + tx;
        g_XTh[o] = h;
        g_XTl[o] = __float2bfloat16(v - __bfloat162float(h));
    }
}

// ------------------------------ HMMA GEMM ---------------------------------
#define KC      64
#define NCH     (MM / KC)
#define TA      32768
#define TB      16384
#define ST_SZ   (2 * TA + 2 * TB)
#define STAGES  2
#define SM_GEMM (STAGES * ST_SZ)

__device__ __forceinline__ void load_chunk(
    uint32_t st,
    const __nv_bfloat16* __restrict__ Ah, const __nv_bfloat16* __restrict__ Al,
    const __nv_bfloat16* __restrict__ Bh, const __nv_bfloat16* __restrict__ Bl,
    int m0, int n0, int k0, int tid)
{
#pragma unroll
    for (int t = 0; t < 24; ++t) {
        int idx = tid + t * 256;
        if (idx < 4096) {
            int sp  = idx >> 11;
            int r   = (idx >> 3) & 255;
            int seg = idx & 7;
            const __nv_bfloat16* src = sp ? Al : Ah;
            cp16(st + sp * TA + sw128(r * 128 + seg * 16),
                 src + (size_t)(m0 + r) * MM + k0 + seg * 8);
        } else {
            int j   = idx - 4096;
            int sp  = j >> 10;
            int r   = (j >> 3) & 127;
            int seg = j & 7;
            const __nv_bfloat16* src = sp ? Bl : Bh;
            cp16(st + 2 * TA + sp * TB + sw128(r * 128 + seg * 16),
                 src + (size_t)(n0 + r) * MM + k0 + seg * 8);
        }
    }
}

// WRITEMODE 0: fp16 into g_pad interior.  1: bf16 hi/lo split to outH/outL.
template <int WRITEMODE>
__global__ __launch_bounds__(256, 1) void gemm_hmma_kernel(
    const __nv_bfloat16* __restrict__ Ah, const __nv_bfloat16* __restrict__ Al,
    const __nv_bfloat16* __restrict__ Bh, const __nv_bfloat16* __restrict__ Bl,
    __half* __restrict__ outP, __nv_bfloat16* __restrict__ outH,
    __nv_bfloat16* __restrict__ outL)
{
    extern __shared__ char smem[];
    uint32_t sb = smem_u32(smem);
    int tid = threadIdx.x, wid = tid >> 5, lane = tid & 31;
    int m0 = blockIdx.y * 256, n0 = blockIdx.x * 128;
    int wm = wid >> 1, wn = wid & 1;

    float acc[4][8][4];
#pragma unroll
    for (int i = 0; i < 4; i++)
#pragma unroll
        for (int j = 0; j < 8; j++)
#pragma unroll
            for (int q = 0; q < 4; q++) acc[i][j][q] = 0.0f;

    int aRow  = wm * 64 + (lane & 7) + ((lane >> 3) & 1) * 8;
    int aSegB = lane >> 4;
    uint32_t aXor  = (uint32_t)(aRow & 7) << 4;
    uint32_t aBase = (uint32_t)aRow * 128;
    int bRow  = wn * 64 + (lane & 7) + ((lane >> 4) & 1) * 8;
    int bSegB = (lane >> 3) & 1;
    uint32_t bXor  = (uint32_t)(bRow & 7) << 4;
    uint32_t bBase = (uint32_t)bRow * 128;

    load_chunk(sb + 0 * ST_SZ, Ah, Al, Bh, Bl, m0, n0, 0 * KC, tid); CP_COMMIT();
    load_chunk(sb + 1 * ST_SZ, Ah, Al, Bh, Bl, m0, n0, 1 * KC, tid); CP_COMMIT();

    for (int c = 0; c < NCH; ++c) {
        if (c + 1 < NCH) CP_WAIT(1);
        else             CP_WAIT(0);
        __syncthreads();

        uint32_t st = sb + (c & 1) * ST_SZ;
        uint32_t sAh = st, sAl = st + TA, sBh = st + 2 * TA, sBl = st + 2 * TA + TB;

#pragma unroll
        for (int ks = 0; ks < 4; ++ks) {
            uint32_t aSegOff = (uint32_t)(((ks * 2 + aSegB) * 16) ^ aXor);
            uint32_t bSegOff = (uint32_t)(((ks * 2 + bSegB) * 16) ^ bXor);
            uint32_t bh[4][4], bl[4][4];
#pragma unroll
            for (int p = 0; p < 4; ++p) {
                uint32_t off = bBase + p * 2048 + bSegOff;
                ldsm4(bh[p][0], bh[p][1], bh[p][2], bh[p][3], sBh + off);
                ldsm4(bl[p][0], bl[p][1], bl[p][2], bl[p][3], sBl + off);
            }
#pragma unroll
            for (int mt = 0; mt < 4; ++mt) {
                uint32_t ah[4], al[4];
                uint32_t off = aBase + mt * 2048 + aSegOff;
                ldsm4(ah[0], ah[1], ah[2], ah[3], sAh + off);
                ldsm4(al[0], al[1], al[2], al[3], sAl + off);
#pragma unroll
                for (int nt = 0; nt < 8; ++nt) {
                    const uint32_t* pbh = &bh[nt >> 1][(nt & 1) * 2];
                    const uint32_t* pbl = &bl[nt >> 1][(nt & 1) * 2];
                    mma16816(acc[mt][nt], ah, pbh);
                    mma16816(acc[mt][nt], ah, pbl);
                    mma16816(acc[mt][nt], al, pbh);
                }
            }
        }
        __syncthreads();
        if (c + 2 < NCH)
            load_chunk(sb + (c & 1) * ST_SZ, Ah, Al, Bh, Bl,
                       m0, n0, (c + 2) * KC, tid);
        CP_COMMIT();
    }

#pragma unroll
    for (int mt = 0; mt < 4; ++mt)
#pragma unroll
        for (int nt = 0; nt < 8; ++nt) {
#pragma unroll
            for (int h = 0; h < 2; ++h) {
                int row = m0 + wm * 64 + mt * 16 + (lane >> 2) + h * 8;
                int col = n0 + wn * 64 + nt * 8 + (lane & 3) * 2;
                float v0 = acc[mt][nt][h * 2 + 0];
                float v1 = acc[mt][nt][h * 2 + 1];
                if (WRITEMODE == 0) {
                    size_t o = (size_t)(row + PADB) * PPS + col + PADB;
                    outP[o]     = __float2half(v0);
                    outP[o + 1] = __float2half(v1);
                } else {
                    __nv_bfloat16 h0 = __float2bfloat16(v0);
                    __nv_bfloat16 h1 = __float2bfloat16(v1);
                    __nv_bfloat16 l0 = __float2bfloat16(v0 - __bfloat162float(h0));
                    __nv_bfloat16 l1 = __float2bfloat16(v1 - __bfloat162float(h1));
                    size_t o = (size_t)row * MM + col;
                    __nv_bfloat162 hp; hp.x = h0; hp.y = h1;
                    __nv_bfloat162 lp; lp.x = l0; lp.y = l1;
                    *(__nv_bfloat162*)&outH[o] = hp;
                    *(__nv_bfloat162*)&outL[o] = lp;
                }
            }
        }
}

// ------------------------------ tiled radon --------------------------------
// fp16 footprint; x-origin aligned to 8 halves (16B); fast path one cp16 per
// 8 halves, slow (wrap) path scalar LDG->STS.  Bilinear in fp32 after cvt.
#define RSW 104                  // smem row stride in halves, multiple of 8
#define RSH 95
#define RMAGIC 12582912.0f       // 1.5 * 2^23
#define RMAGIC_I 0x4B400000

__global__ __launch_bounds__(256) void radon_tiled_kernel() {
    __shared__ __half sm[RSH * RSW];
    __shared__ float red[256];

    int a  = blockIdx.z;
    int x0 = blockIdx.x * 64;
    int y0 = blockIdx.y * 64;
    int tid = threadIdx.x, wid = tid >> 5, lane = tid & 31;

    float ang = (float)(3.141592653589793 * (double)a / 31.0);
    float ca = cosf(ang);
    float sa = sinf(ang);
    const float cen = (float)(PP / 2);
    float c1 = cen * (ca + sa - 1.0f);
    float c2 = cen * (ca - sa - 1.0f);

    float xf0 = (float)x0, xf1 = (float)(x0 + 63);
    float yf0 = (float)y0, yf1 = (float)(y0 + 63);
    float u00 = ca * xf0 + sa * yf0 - c1, u01 = ca * xf0 + sa * yf1 - c1;
    float u10 = ca * xf1 + sa * yf0 - c1, u11 = ca * xf1 + sa * yf1 - c1;
    float v00 = -sa * xf0 + ca * yf0 - c2, v01 = -sa * xf0 + ca * yf1 - c2;
    float v10 = -sa * xf1 + ca * yf0 - c2, v11 = -sa * xf1 + ca * yf1 - c2;
    float umin = fminf(fminf(u00, u01), fminf(u10, u11));
    float umax = fmaxf(fmaxf(u00, u01), fmaxf(u10, u11));
    float vmin = fminf(fminf(v00, v01), fminf(v10, v11));
    float vmax = fmaxf(fmaxf(v00, v01), fmaxf(v10, v11));

    int u0i = (int)floorf(umin) - 1;
    int v0i = (int)floorf(vmin) - 1;
    int W = (int)floorf(umax) + 2 - u0i + 1;
    int H = (int)floorf(vmax) + 2 - v0i + 1;

    int u0m = u0i % PP; if (u0m < 0) u0m += PP;
    int v0m = v0i % PP; if (v0m < 0) v0m += PP;

    // shift origin down to 8-half (16B) alignment
    int sft  = u0m & 7;
    int u0s  = u0i - sft;
    int u0ms = u0m - sft;
    int W8   = (W + sft + 7) & ~7;

    uint32_t smb = smem_u32(sm);
    if (u0ms + W8 <= PP) {
        int nq = W8 >> 3;
        for (int r = wid; r < H; r += 8) {
            int rm = v0m + r; if (rm >= PP) rm -= PP;
            const __half* src = g_pad + (size_t)rm * PPS + u0ms;
            uint32_t drow = smb + (uint32_t)(r * RSW) * 2;
            for (int q = lane; q < nq; q += 32)
                cp16(drow + (uint32_t)q * 16, src + q * 8);
        }
    } else {
        for (int r = wid; r < H; r += 8) {
            int rm = v0m + r; if (rm >= PP) rm -= PP;
            const __half* rowp = g_pad + (size_t)rm * PPS;
            for (int c = lane; c < W8; c += 32) {
                int cm = u0ms + c; if (cm >= PP) cm -= PP;
                sm[r * RSW + c] = rowp[cm];
            }
        }
    }
    CP_COMMIT();

    int xl   = tid & 63;
    int ysub = tid >> 6;
    int x    = x0 + xl;
    float xf = (float)x;
    float bx = ca * xf - c1;
    float by = -sa * xf - c2;

    int ybeg = y0 + ysub * 16;
    float ybf  = (float)ybeg;
    float xin0 = fmaf(sa, ybf, bx);
    float yin0 = fmaf(ca, ybf, by);
    float fx0 = floorf(xin0);
    float fy0 = floorf(yin0);
    float wx0 = xin0 - fx0;
    float wy0 = yin0 - fy0;
    int   base0 = ((int)fy0 - v0i) * RSW + ((int)fx0 - u0s);

    CP_WAIT(0);
    __syncthreads();

    float acc0 = 0.0f, acc1 = 0.0f;
#pragma unroll
    for (int i = 0; i < 16; ++i) {
        float tx = fmaf((float)i, sa, wx0);
        float ty = fmaf((float)i, ca, wy0);
        float ux = tx + RMAGIC;
        float uy = ty + RMAGIC;
        int nx = __float_as_int(ux) - RMAGIC_I;
        int ny = __float_as_int(uy) - RMAGIC_I;
        float wx = tx - (ux - RMAGIC);
        float wy = ty - (uy - RMAGIC);
        if (wx < 0.0f) { wx += 1.0f; nx -= 1; }
        if (wy < 0.0f) { wy += 1.0f; ny -= 1; }
        const __half* p = sm + (base0 + ny * RSW + nx);
        float s00 = __half2float(p[0]);
        float s01 = __half2float(p[1]);
        float s10 = __half2float(p[RSW]);
        float s11 = __half2float(p[RSW + 1]);
        float top = fmaf(wx, s01 - s00, s00);
        float bot = fmaf(wx, s11 - s10, s10);
        float res = fmaf(wy, bot - top, top);
        float g = (ybeg + i < PP) ? 1.0f : 0.0f;
        if (i & 1) acc1 = fmaf(g, res, acc1);
        else       acc0 = fmaf(g, res, acc0);
    }
    float acc = acc0 + acc1;

    __syncthreads();
    red[ysub * 64 + xl] = acc;
    __syncthreads();
    if (tid < 64) {
        float s = ((red[tid] + red[64 + tid]) + red[128 + tid]) + red[192 + tid];
        int xo = x0 + tid;
        if (xo < PP)
            g_lpart[(size_t)blockIdx.y * TOT + a * PP + xo] = s;
    }
}

// --------------------------- reduce / normalize ----------------------------
__global__ void reduce_max_kernel() {
    __shared__ float smax[256];
    int idx = blockIdx.x * 256 + threadIdx.x;
    float v = -__int_as_float(0x7f800000);
    if (idx < TOT) {
        float s = 0.0f;
        for (int p = 0; p < NYT; p++) s += g_lpart[(size_t)p * TOT + idx];
        g_lines[idx] = s;
        v = s;
    }
    smax[threadIdx.x] = v;
    __syncthreads();
    for (int o = 128; o > 0; o >>= 1) {
        if (threadIdx.x < o)
            smax[threadIdx.x] = fmaxf(smax[threadIdx.x], smax[threadIdx.x + o]);
        __syncthreads();
    }
    if (threadIdx.x == 0) {
        unsigned u = __float_as_uint(smax[0]);
        unsigned enc = (u & 0x80000000u) ? ~u : (u | 0x80000000u);
        atomicMax(&g_maxbits, enc);
    }
}

__global__ void normalize_kernel(float* __restrict__ out) {
    int idx = blockIdx.x * 256 + threadIdx.x;
    if (idx >= TOT) return;
    unsigned u = g_maxbits;
    float mx = (u & 0x80000000u) ? __uint_as_float(u & 0x7fffffffu)
                                 : __uint_as_float(~u);
    int x = idx >> 5;
    int a = idx & 31;
    out[idx] = g_lines[a * PP + x] / mx;
}

// ---------------------------------------------------------------------------
extern "C" void kernel_launch(void* const* d_in, const int* in_sizes, int n_in,
                              void* d_out, int out_size) {
    const float* img = (const float*)d_in[0];
    float* out = (float*)d_out;

    static int s_init = 0;
    if (!s_init) {
        cudaFuncSetAttribute(gemm_hmma_kernel<0>,
                             cudaFuncAttributeMaxDynamicSharedMemorySize, SM_GEMM);
        cudaFuncSetAttribute(gemm_hmma_kernel<1>,
                             cudaFuncAttributeMaxDynamicSharedMemorySize, SM_GEMM);
        s_init = 1;
    }

    init_border_kernel<<<(NB1 + NB2 + 255) / 256, 256>>>();
    gen_dct_kernel<<<(MM * MM + 255) / 256, 256>>>();
    transpose_split_kernel<<<dim3(64, 64), dim3(32, 8)>>>(img);

    __nv_bfloat16 *pCh, *pCl, *pXTh, *pXTl, *pTh, *pTl;
    cudaGetSymbolAddress((void**)&pCh,  g_Ch);
    cudaGetSymbolAddress((void**)&pCl,  g_Cl);
    cudaGetSymbolAddress((void**)&pXTh, g_XTh);
    cudaGetSymbolAddress((void**)&pXTl, g_XTl);
    cudaGetSymbolAddress((void**)&pTh,  g_Th);
    cudaGetSymbolAddress((void**)&pTl,  g_Tl);
    __half* pPad;
    cudaGetSymbolAddress((void**)&pPad, g_pad);

    dim3 gg(MM / 128, MM / 256);
    gemm_hmma_kernel<1><<<gg, 256, SM_GEMM>>>(pCh, pCl, pXTh, pXTl,
                                              nullptr, pTh, pTl);
    gemm_hmma_kernel<0><<<gg, 256, SM_GEMM>>>(pTh, pTl, pCh, pCl,
                                              pPad, nullptr, nullptr);

    dim3 rg(NXT, NYT, NANG);
    radon_tiled_kernel<<<rg, 256>>>();

    reduce_max_kernel<<<(TOT + 255) / 256, 256>>>();
    normalize_kernel<<<(TOT + 255) / 256, 256>>>(out);
}

// round 11
// speedup vs baseline: 1.0822x; 1.0822x over previous
#include <cuda_runtime.h>
#include <cuda_bf16.h>
#include <cstdint>

// ---------------------------------------------------------------------------
// image_prj: D = dct2(image) [2048x2048, ortho] -> pad to 2198x2198 ->
// 32-angle radon (bilinear, WRAP) -> lines^T / max
// GEMMs: mma.sync bf16x3 split.  Radon: 16B cp.async footprint staging
// + bias-round convert-free bilinear (fp32 pad, issue-minimized loop).
// ---------------------------------------------------------------------------

#define MM    2048
#define PP    2198
#define PPS   2200               // padded row stride (16B-aligned fp32 rows)
#define PADB  75
#define NANG  32
#define TOT   (NANG * PP)
#define NYT   35
#define NXT   35

__device__ __nv_bfloat16 g_Ch[MM * MM], g_Cl[MM * MM];
__device__ __nv_bfloat16 g_XTh[MM * MM], g_XTl[MM * MM];
__device__ __nv_bfloat16 g_Th[MM * MM], g_Tl[MM * MM];
__device__ float    g_pad[PP * PPS];
__device__ float    g_lpart[NYT * TOT];
__device__ float    g_lines[TOT];
__device__ unsigned g_maxbits;

// ------------------------------ PTX helpers -------------------------------
__device__ __forceinline__ uint32_t smem_u32(const void* p) {
    uint32_t a;
    asm("{ .reg .u64 t; cvta.to.shared.u64 t, %1; cvt.u32.u64 %0, t; }"
        : "=r"(a) : "l"(p));
    return a;
}
#define CP_COMMIT() asm volatile("cp.async.commit_group;" ::: "memory")
#define CP_WAIT(n)  asm volatile("cp.async.wait_group %0;" :: "n"(n) : "memory")

__device__ __forceinline__ void cp16(uint32_t dst, const void* src) {
    asm volatile("cp.async.cg.shared.global [%0], [%1], 16;"
                 :: "r"(dst), "l"(src) : "memory");
}
__device__ __forceinline__ void cp4(uint32_t dst, const void* src) {
    asm volatile("cp.async.ca.shared.global [%0], [%1], 4;"
                 :: "r"(dst), "l"(src) : "memory");
}
__device__ __forceinline__ void ldsm4(uint32_t& r0, uint32_t& r1,
                                      uint32_t& r2, uint32_t& r3, uint32_t a) {
    asm volatile("ldmatrix.sync.aligned.m8n8.x4.shared.b16 {%0,%1,%2,%3}, [%4];"
                 : "=r"(r0), "=r"(r1), "=r"(r2), "=r"(r3) : "r"(a));
}
__device__ __forceinline__ void mma16816(float* d, const uint32_t* a,
                                         const uint32_t* b) {
    asm volatile("mma.sync.aligned.m16n8k16.row.col.f32.bf16.bf16.f32 "
                 "{%0,%1,%2,%3}, {%4,%5,%6,%7}, {%8,%9}, {%0,%1,%2,%3};"
                 : "+f"(d[0]), "+f"(d[1]), "+f"(d[2]), "+f"(d[3])
                 : "r"(a[0]), "r"(a[1]), "r"(a[2]), "r"(a[3]),
                   "r"(b[0]), "r"(b[1]));
}
__device__ __forceinline__ uint32_t sw128(uint32_t b) { return b ^ ((b >> 3) & 0x70); }

// --------------------------- merged prep kernel ----------------------------
// one launch: [0, NBB) border zero, [NBB, NBB+NDB) dct gen, rest transpose.
#define NB1 (150 * PP)
#define NB2 (MM * 150)
#define NBB ((NB1 + NB2 + 255) / 256)       // 2488 blocks
#define NDB (MM * MM / 256)                 // 16384 blocks
#define NTB (64 * 64)                       // 4096 blocks

__global__ void prep_kernel(const float* __restrict__ img) {
    __shared__ float tile[32][33];
    int b = blockIdx.x;
    int tid = threadIdx.x;

    if (b < NBB) {                         // ---- pad border zero ----
        int idx = b * 256 + tid;
        if (idx == 0) g_maxbits = 0u;
        if (idx < NB1) {
            int r = idx / PP, c = idx % PP;
            int row = (r < 75) ? r : (2123 + r - 75);
            g_pad[(size_t)row * PPS + c] = 0.0f;
        } else if (idx < NB1 + NB2) {
            int j = idx - NB1;
            int r = j / 150, c = j % 150;
            int col = (c < 75) ? c : (2123 + c - 75);
            g_pad[(size_t)(75 + r) * PPS + col] = 0.0f;
        }
        return;
    }
    b -= NBB;
    if (b < NDB) {                         // ---- DCT matrix gen ----
        int idx = b * 256 + tid;
        int k = idx >> 11;
        int n = idx & (MM - 1);
        int r = ((2 * n + 1) * k) & (4 * MM - 1);
        float t = (float)r * (1.0f / (2.0f * MM));
        float c = cospif(t);
        float s = (k == 0) ? 0.022097086912079608f : 0.03125f;
        float v = s * c;
        __nv_bfloat16 h = __float2bfloat16(v);
        g_Ch[idx] = h;
        g_Cl[idx] = __float2bfloat16(v - __bfloat162float(h));
        return;
    }
    b -= NDB;                              // ---- transpose + split ----
    {
        int bx = (b & 63) * 32, by = (b >> 6) * 32;
        int tx = tid & 31, ty = tid >> 5;
#pragma unroll
        for (int i = 0; i < 4; i++)
            tile[ty + i * 8][tx] = img[(size_t)(by + ty + i * 8) * MM + bx + tx];
        __syncthreads();
#pragma unroll
        for (int i = 0; i < 4; i++) {
            float v = tile[tx][ty + i * 8];
            __nv_bfloat16 h = __float2bfloat16(v);
            size_t o = (size_t)(bx + ty + i * 8) * MM + by + tx;
            g_XTh[o] = h;
            g_XTl[o] = __float2bfloat16(v - __bfloat162float(h));
        }
    }
}

// ------------------------------ HMMA GEMM ---------------------------------
#define KC      64
#define NCH     (MM / KC)
#define TA      32768
#define TB      16384
#define ST_SZ   (2 * TA + 2 * TB)
#define STAGES  2
#define SM_GEMM (STAGES * ST_SZ)

__device__ __forceinline__ void load_chunk(
    uint32_t st,
    const __nv_bfloat16* __restrict__ Ah, const __nv_bfloat16* __restrict__ Al,
    const __nv_bfloat16* __restrict__ Bh, const __nv_bfloat16* __restrict__ Bl,
    int m0, int n0, int k0, int tid)
{
#pragma unroll
    for (int t = 0; t < 24; ++t) {
        int idx = tid + t * 256;
        if (idx < 4096) {
            int sp  = idx >> 11;
            int r   = (idx >> 3) & 255;
            int seg = idx & 7;
            const __nv_bfloat16* src = sp ? Al : Ah;
            cp16(st + sp * TA + sw128(r * 128 + seg * 16),
                 src + (size_t)(m0 + r) * MM + k0 + seg * 8);
        } else {
            int j   = idx - 4096;
            int sp  = j >> 10;
            int r   = (j >> 3) & 127;
            int seg = j & 7;
            const __nv_bfloat16* src = sp ? Bl : Bh;
            cp16(st + 2 * TA + sp * TB + sw128(r * 128 + seg * 16),
                 src + (size_t)(n0 + r) * MM + k0 + seg * 8);
        }
    }
}

template <int WRITEMODE>
__global__ __launch_bounds__(256, 1) void gemm_hmma_kernel(
    const __nv_bfloat16* __restrict__ Ah, const __nv_bfloat16* __restrict__ Al,
    const __nv_bfloat16* __restrict__ Bh, const __nv_bfloat16* __restrict__ Bl,
    float* __restrict__ outF, __nv_bfloat16* __restrict__ outH,
    __nv_bfloat16* __restrict__ outL)
{
    extern __shared__ char smem[];
    uint32_t sb = smem_u32(smem);
    int tid = threadIdx.x, wid = tid >> 5, lane = tid & 31;
    int m0 = blockIdx.y * 256, n0 = blockIdx.x * 128;
    int wm = wid >> 1, wn = wid & 1;

    float acc[4][8][4];
#pragma unroll
    for (int i = 0; i < 4; i++)
#pragma unroll
        for (int j = 0; j < 8; j++)
#pragma unroll
            for (int q = 0; q < 4; q++) acc[i][j][q] = 0.0f;

    int aRow  = wm * 64 + (lane & 7) + ((lane >> 3) & 1) * 8;
    int aSegB = lane >> 4;
    uint32_t aXor  = (uint32_t)(aRow & 7) << 4;
    uint32_t aBase = (uint32_t)aRow * 128;
    int bRow  = wn * 64 + (lane & 7) + ((lane >> 4) & 1) * 8;
    int bSegB = (lane >> 3) & 1;
    uint32_t bXor  = (uint32_t)(bRow & 7) << 4;
    uint32_t bBase = (uint32_t)bRow * 128;

    load_chunk(sb + 0 * ST_SZ, Ah, Al, Bh, Bl, m0, n0, 0 * KC, tid); CP_COMMIT();
    load_chunk(sb + 1 * ST_SZ, Ah, Al, Bh, Bl, m0, n0, 1 * KC, tid); CP_COMMIT();

    for (int c = 0; c < NCH; ++c) {
        if (c + 1 < NCH) CP_WAIT(1);
        else             CP_WAIT(0);
        __syncthreads();

        uint32_t st = sb + (c & 1) * ST_SZ;
        uint32_t sAh = st, sAl = st + TA, sBh = st + 2 * TA, sBl = st + 2 * TA + TB;

#pragma unroll
        for (int ks = 0; ks < 4; ++ks) {
            uint32_t aSegOff = (uint32_t)(((ks * 2 + aSegB) * 16) ^ aXor);
            uint32_t bSegOff = (uint32_t)(((ks * 2 + bSegB) * 16) ^ bXor);
            uint32_t bh[4][4], bl[4][4];
#pragma unroll
            for (int p = 0; p < 4; ++p) {
                uint32_t off = bBase + p * 2048 + bSegOff;
                ldsm4(bh[p][0], bh[p][1], bh[p][2], bh[p][3], sBh + off);
                ldsm4(bl[p][0], bl[p][1], bl[p][2], bl[p][3], sBl + off);
            }
#pragma unroll
            for (int mt = 0; mt < 4; ++mt) {
                uint32_t ah[4], al[4];
                uint32_t off = aBase + mt * 2048 + aSegOff;
                ldsm4(ah[0], ah[1], ah[2], ah[3], sAh + off);
                ldsm4(al[0], al[1], al[2], al[3], sAl + off);
#pragma unroll
                for (int nt = 0; nt < 8; ++nt) {
                    const uint32_t* pbh = &bh[nt >> 1][(nt & 1) * 2];
                    const uint32_t* pbl = &bl[nt >> 1][(nt & 1) * 2];
                    mma16816(acc[mt][nt], ah, pbh);
                    mma16816(acc[mt][nt], ah, pbl);
                    mma16816(acc[mt][nt], al, pbh);
                }
            }
        }
        __syncthreads();
        if (c + 2 < NCH)
            load_chunk(sb + (c & 1) * ST_SZ, Ah, Al, Bh, Bl,
                       m0, n0, (c + 2) * KC, tid);
        CP_COMMIT();
    }

#pragma unroll
    for (int mt = 0; mt < 4; ++mt)
#pragma unroll
        for (int nt = 0; nt < 8; ++nt) {
#pragma unroll
            for (int h = 0; h < 2; ++h) {
                int row = m0 + wm * 64 + mt * 16 + (lane >> 2) + h * 8;
                int col = n0 + wn * 64 + nt * 8 + (lane & 3) * 2;
                float v0 = acc[mt][nt][h * 2 + 0];
                float v1 = acc[mt][nt][h * 2 + 1];
                if (WRITEMODE == 0) {
                    size_t o = (size_t)(row + PADB) * PPS + col + PADB;
                    outF[o]     = v0;
                    outF[o + 1] = v1;
                } else {
                    __nv_bfloat16 h0 = __float2bfloat16(v0);
                    __nv_bfloat16 h1 = __float2bfloat16(v1);
                    __nv_bfloat16 l0 = __float2bfloat16(v0 - __bfloat162float(h0));
                    __nv_bfloat16 l1 = __float2bfloat16(v1 - __bfloat162float(h1));
                    size_t o = (size_t)row * MM + col;
                    __nv_bfloat162 hp; hp.x = h0; hp.y = h1;
                    __nv_bfloat162 lp; lp.x = l0; lp.y = l1;
                    *(__nv_bfloat162*)&outH[o] = hp;
                    *(__nv_bfloat162*)&outL[o] = lp;
                }
            }
        }
}

// ------------------------------ tiled radon --------------------------------
// fp32 footprint via 16B cp.async (aligned to 4 floats); bias-round floor:
// nx = round(t-0.5) via magic add (tie flips land on bilinear-continuous
// points -> value unchanged).  Per-sample: no converts, no predicated fixes.
#define RSW 100
#define RSH 95
#define RMAGIC 12582912.0f       // 1.5 * 2^23
#define RMAGIC_I 0x4B400000

// one sample: txm/tym are (coord - floorbase - 0.5)
__device__ __forceinline__ float radon_sample(
    const float* __restrict__ sm, int base0, float txm, float tym)
{
    float ux = txm + RMAGIC;
    float uy = tym + RMAGIC;
    int   nx = __float_as_int(ux) - RMAGIC_I;    // round(txm) = floor(tx)
    int   ny = __float_as_int(uy) - RMAGIC_I;
    float wx = (txm - (ux - RMAGIC)) + 0.5f;     // frac in [0,1]
    float wy = (tym - (uy - RMAGIC)) + 0.5f;
    const float* p = sm + (base0 + ny * RSW + nx);
    float s00 = p[0], s01 = p[1], s10 = p[RSW], s11 = p[RSW + 1];
    float top = fmaf(wx, s01 - s00, s00);
    float bot = fmaf(wx, s11 - s10, s10);
    return fmaf(wy, bot - top, top);
}

__global__ __launch_bounds__(256) void radon_tiled_kernel() {
    __shared__ float sm[RSH * RSW];
    __shared__ float red[256];

    int a  = blockIdx.z;
    int x0 = blockIdx.x * 64;
    int y0 = blockIdx.y * 64;
    int tid = threadIdx.x, wid = tid >> 5, lane = tid & 31;

    float ang = (float)(3.141592653589793 * (double)a / 31.0);
    float ca = cosf(ang);
    float sa = sinf(ang);
    const float cen = (float)(PP / 2);
    float c1 = cen * (ca + sa - 1.0f);
    float c2 = cen * (ca - sa - 1.0f);

    float xf0 = (float)x0, xf1 = (float)(x0 + 63);
    float yf0 = (float)y0, yf1 = (float)(y0 + 63);
    float u00 = ca * xf0 + sa * yf0 - c1, u01 = ca * xf0 + sa * yf1 - c1;
    float u10 = ca * xf1 + sa * yf0 - c1, u11 = ca * xf1 + sa * yf1 - c1;
    float v00 = -sa * xf0 + ca * yf0 - c2, v01 = -sa * xf0 + ca * yf1 - c2;
    float v10 = -sa * xf1 + ca * yf0 - c2, v11 = -sa * xf1 + ca * yf1 - c2;
    float umin = fminf(fminf(u00, u01), fminf(u10, u11));
    float umax = fmaxf(fmaxf(u00, u01), fmaxf(u10, u11));
    float vmin = fminf(fminf(v00, v01), fminf(v10, v11));
    float vmax = fmaxf(fmaxf(v00, v01), fmaxf(v10, v11));

    int u0i = (int)floorf(umin) - 1;
    int v0i = (int)floorf(vmin) - 1;
    int W = (int)floorf(umax) + 2 - u0i + 1;
    int H = (int)floorf(vmax) + 2 - v0i + 1;

    int u0m = u0i % PP; if (u0m < 0) u0m += PP;
    int v0m = v0i % PP; if (v0m < 0) v0m += PP;

    int sft  = u0m & 3;
    int u0s  = u0i - sft;
    int u0ms = u0m - sft;
    int W4   = (W + sft + 3) & ~3;

    uint32_t smb = smem_u32(sm);
    if (u0ms + W4 <= PP) {
        int nq = W4 >> 2;
        for (int r = wid; r < H; r += 8) {
            int rm = v0m + r; if (rm >= PP) rm -= PP;
            const float* src = g_pad + (size_t)rm * PPS + u0ms;
            uint32_t drow = smb + (uint32_t)(r * RSW) * 4;
            for (int q = lane; q < nq; q += 32)
                cp16(drow + (uint32_t)q * 16, src + q * 4);
        }
    } else {
        for (int r = wid; r < H; r += 8) {
            int rm = v0m + r; if (rm >= PP) rm -= PP;
            const float* rowp = g_pad + (size_t)rm * PPS;
            uint32_t drow = smb + (uint32_t)(r * RSW) * 4;
            for (int c = lane; c < W4; c += 32) {
                int cm = u0ms + c; if (cm >= PP) cm -= PP;
                cp4(drow + (uint32_t)c * 4, rowp + cm);
            }
        }
    }
    CP_COMMIT();

    int xl   = tid & 63;
    int ysub = tid >> 6;
    int x    = x0 + xl;
    float xf = (float)x;
    float bx = ca * xf - c1;
    float by = -sa * xf - c2;

    int ybeg = y0 + ysub * 16;
    float ybf  = (float)ybeg;
    float xin0 = fmaf(sa, ybf, bx);
    float yin0 = fmaf(ca, ybf, by);
    float fx0 = floorf(xin0);
    float fy0 = floorf(yin0);
    float wx0m = (xin0 - fx0) - 0.5f;     // biased frac at strip base
    float wy0m = (yin0 - fy0) - 0.5f;
    int   base0 = ((int)fy0 - v0i) * RSW + ((int)fx0 - u0s);

    CP_WAIT(0);
    __syncthreads();

    float acc0 = 0.0f, acc1 = 0.0f;
    if (y0 + 64 <= PP) {
        // fast path: no y guard
#pragma unroll
        for (int i = 0; i < 16; ++i) {
            float r = radon_sample(sm, base0,
                                   fmaf((float)i, sa, wx0m),
                                   fmaf((float)i, ca, wy0m));
            if (i & 1) acc1 += r; else acc0 += r;
        }
    } else {
#pragma unroll
        for (int i = 0; i < 16; ++i) {
            float r = radon_sample(sm, base0,
                                   fmaf((float)i, sa, wx0m),
                                   fmaf((float)i, ca, wy0m));
            float g = (ybeg + i < PP) ? 1.0f : 0.0f;
            if (i & 1) acc1 = fmaf(g, r, acc1);
            else       acc0 = fmaf(g, r, acc0);
        }
    }
    float acc = acc0 + acc1;

    __syncthreads();
    red[ysub * 64 + xl] = acc;
    __syncthreads();
    if (tid < 64) {
        float s = ((red[tid] + red[64 + tid]) + red[128 + tid]) + red[192 + tid];
        int xo = x0 + tid;
        if (xo < PP)
            g_lpart[(size_t)blockIdx.y * TOT + a * PP + xo] = s;
    }
}

// --------------------------- reduce / normalize ----------------------------
__global__ void reduce_max_kernel() {
    __shared__ float smax[256];
    int idx = blockIdx.x * 256 + threadIdx.x;
    float v = -__int_as_float(0x7f800000);
    if (idx < TOT) {
        float s = 0.0f;
        for (int p = 0; p < NYT; p++) s += g_lpart[(size_t)p * TOT + idx];
        g_lines[idx] = s;
        v = s;
    }
    smax[threadIdx.x] = v;
    __syncthreads();
    for (int o = 128; o > 0; o >>= 1) {
        if (threadIdx.x < o)
            smax[threadIdx.x] = fmaxf(smax[threadIdx.x], smax[threadIdx.x + o]);
        __syncthreads();
    }
    if (threadIdx.x == 0) {
        unsigned u = __float_as_uint(smax[0]);
        unsigned enc = (u & 0x80000000u) ? ~u : (u | 0x80000000u);
        atomicMax(&g_maxbits, enc);
    }
}

__global__ void normalize_kernel(float* __restrict__ out) {
    int idx = blockIdx.x * 256 + threadIdx.x;
    if (idx >= TOT) return;
    unsigned u = g_maxbits;
    float mx = (u & 0x80000000u) ? __uint_as_float(u & 0x7fffffffu)
                                 : __uint_as_float(~u);
    int x = idx >> 5;
    int a = idx & 31;
    out[idx] = g_lines[a * PP + x] / mx;
}

// ---------------------------------------------------------------------------
extern "C" void kernel_launch(void* const* d_in, const int* in_sizes, int n_in,
                              void* d_out, int out_size) {
    const float* img = (const float*)d_in[0];
    float* out = (float*)d_out;

    static int s_init = 0;
    if (!s_init) {
        cudaFuncSetAttribute(gemm_hmma_kernel<0>,
                             cudaFuncAttributeMaxDynamicSharedMemorySize, SM_GEMM);
        cudaFuncSetAttribute(gemm_hmma_kernel<1>,
                             cudaFuncAttributeMaxDynamicSharedMemorySize, SM_GEMM);
        s_init = 1;
    }

    prep_kernel<<<NBB + NDB + NTB, 256>>>(img);

    __nv_bfloat16 *pCh, *pCl, *pXTh, *pXTl, *pTh, *pTl;
    cudaGetSymbolAddress((void**)&pCh,  g_Ch);
    cudaGetSymbolAddress((void**)&pCl,  g_Cl);
    cudaGetSymbolAddress((void**)&pXTh, g_XTh);
    cudaGetSymbolAddress((void**)&pXTl, g_XTl);
    cudaGetSymbolAddress((void**)&pTh,  g_Th);
    cudaGetSymbolAddress((void**)&pTl,  g_Tl);
    float* pPad;
    cudaGetSymbolAddress((void**)&pPad, g_pad);

    dim3 gg(MM / 128, MM / 256);
    gemm_hmma_kernel<1><<<gg, 256, SM_GEMM>>>(pCh, pCl, pXTh, pXTl,
                                              nullptr, pTh, pTl);
    gemm_hmma_kernel<0><<<gg, 256, SM_GEMM>>>(pTh, pTl, pCh, pCl,
                                              pPad, nullptr, nullptr);

    dim3 rg(NXT, NYT, NANG);
    radon_tiled_kernel<<<rg, 256>>>();

    reduce_max_kernel<<<(TOT + 255) / 256, 256>>>();
    normalize_kernel<<<(TOT + 255) / 256, 256>>>(out);
}

// round 12
// speedup vs baseline: 1.3432x; 1.2412x over previous
#include <cuda_runtime.h>
#include <cuda_bf16.h>
#include <cstdint>

// ---------------------------------------------------------------------------
// image_prj: D = dct2(image) [2048x2048, ortho] -> pad to 2198x2198 ->
// 32-angle radon (bilinear, WRAP) -> lines^T / max
// GEMMs: DCT even/odd symmetry fold -> 4 sub-GEMMs with K=1024 (half FLOPs),
// mma.sync bf16x3 split.  Radon: cp.async tile + bias-round bilinear.
// ---------------------------------------------------------------------------

#define MM    2048
#define HM    1024
#define PP    2198
#define PPS   2200
#define PADB  75
#define NANG  32
#define TOT   (NANG * PP)
#define NYT   35
#define NXT   35

// folded operands (all [rows x 1024], bf16 hi/lo)
__device__ __nv_bfloat16 g_Ceh[HM * HM], g_Cel[HM * HM];   // C even rows
__device__ __nv_bfloat16 g_Coh[HM * HM], g_Col[HM * HM];   // C odd rows
__device__ __nv_bfloat16 g_Bsh[MM * HM], g_Bsl[MM * HM];   // X^T fold-sum
__device__ __nv_bfloat16 g_Bah[MM * HM], g_Bal[MM * HM];   // X^T fold-diff
__device__ __nv_bfloat16 g_Ash[MM * HM], g_Asl[MM * HM];   // tmp fold-sum
__device__ __nv_bfloat16 g_Aah[MM * HM], g_Aal[MM * HM];   // tmp fold-diff
__device__ float    g_tmpF[MM * MM];
__device__ float    g_pad[PP * PPS];
__device__ float    g_lpart[NYT * TOT];
__device__ float    g_lines[TOT];
__device__ unsigned g_maxbits;

// ------------------------------ PTX helpers -------------------------------
__device__ __forceinline__ uint32_t smem_u32(const void* p) {
    uint32_t a;
    asm("{ .reg .u64 t; cvta.to.shared.u64 t, %1; cvt.u32.u64 %0, t; }"
        : "=r"(a) : "l"(p));
    return a;
}
#define CP_COMMIT() asm volatile("cp.async.commit_group;" ::: "memory")
#define CP_WAIT(n)  asm volatile("cp.async.wait_group %0;" :: "n"(n) : "memory")

__device__ __forceinline__ void cp16(uint32_t dst, const void* src) {
    asm volatile("cp.async.cg.shared.global [%0], [%1], 16;"
                 :: "r"(dst), "l"(src) : "memory");
}
__device__ __forceinline__ void cp4(uint32_t dst, const void* src) {
    asm volatile("cp.async.ca.shared.global [%0], [%1], 4;"
                 :: "r"(dst), "l"(src) : "memory");
}
__device__ __forceinline__ void ldsm4(uint32_t& r0, uint32_t& r1,
                                      uint32_t& r2, uint32_t& r3, uint32_t a) {
    asm volatile("ldmatrix.sync.aligned.m8n8.x4.shared.b16 {%0,%1,%2,%3}, [%4];"
                 : "=r"(r0), "=r"(r1), "=r"(r2), "=r"(r3) : "r"(a));
}
__device__ __forceinline__ void mma16816(float* d, const uint32_t* a,
                                         const uint32_t* b) {
    asm volatile("mma.sync.aligned.m16n8k16.row.col.f32.bf16.bf16.f32 "
                 "{%0,%1,%2,%3}, {%4,%5,%6,%7}, {%8,%9}, {%0,%1,%2,%3};"
                 : "+f"(d[0]), "+f"(d[1]), "+f"(d[2]), "+f"(d[3])
                 : "r"(a[0]), "r"(a[1]), "r"(a[2]), "r"(a[3]),
                   "r"(b[0]), "r"(b[1]));
}
__device__ __forceinline__ uint32_t sw128(uint32_t b) { return b ^ ((b >> 3) & 0x70); }
__device__ __forceinline__ void bf16split(float v, __nv_bfloat16& h, __nv_bfloat16& l) {
    h = __float2bfloat16(v);
    l = __float2bfloat16(v - __bfloat162float(h));
}

// --------------------------- merged prep kernel ----------------------------
#define NB1 (150 * PP)
#define NB2 (MM * 150)
#define NBB ((NB1 + NB2 + 255) / 256)      // border-zero blocks
#define NCG (2 * HM * HM / 256)            // 8192: Ce/Co gen
#define NTS ((HM / 32) * (MM / 32))        // 2048: transpose + fold of X

__global__ void prep_kernel(const float* __restrict__ img) {
    __shared__ float ts[32][33];
    __shared__ float ta[32][33];
    int b = blockIdx.x;
    int tid = threadIdx.x;

    if (b < NBB) {                          // ---- pad border zero ----
        int idx = b * 256 + tid;
        if (idx == 0) g_maxbits = 0u;
        if (idx < NB1) {
            int r = idx / PP, c = idx % PP;
            int row = (r < 75) ? r : (2123 + r - 75);
            g_pad[(size_t)row * PPS + c] = 0.0f;
        } else if (idx < NB1 + NB2) {
            int j = idx - NB1;
            int r = j / 150, c = j % 150;
            int col = (c < 75) ? c : (2123 + c - 75);
            g_pad[(size_t)(75 + r) * PPS + col] = 0.0f;
        }
        return;
    }
    b -= NBB;
    if (b < NCG) {                          // ---- Ce/Co generation ----
        int idx = b * 256 + tid;            // [0, 2*1024*1024)
        int par = idx >> 20;
        int mp  = (idx >> 10) & (HM - 1);
        int n   = idx & (HM - 1);
        int k   = 2 * mp + par;
        int r   = ((2 * n + 1) * k) & (4 * MM - 1);
        float t = (float)r * (1.0f / (2.0f * MM));
        float c = cospif(t);
        float s = (k == 0) ? 0.022097086912079608f : 0.03125f;
        float v = s * c;
        __nv_bfloat16 h, l; bf16split(v, h, l);
        size_t o = (size_t)mp * HM + n;
        if (par) { g_Coh[o] = h; g_Col[o] = l; }
        else     { g_Ceh[o] = h; g_Cel[o] = l; }
        return;
    }
    b -= NCG;                               // ---- X transpose + fold ----
    {
        int kt = b & 31, nt = b >> 5;       // k-tiles over [0,1024), n over [0,2048)
        int kb = kt * 32, nb = nt * 32;
        int tx = tid & 31, ty = tid >> 5;
#pragma unroll
        for (int i = 0; i < 4; i++) {
            int k = kb + ty + i * 8;
            float v1 = img[(size_t)k * MM + nb + tx];
            float v2 = img[(size_t)(MM - 1 - k) * MM + nb + tx];
            ts[ty + i * 8][tx] = v1 + v2;
            ta[ty + i * 8][tx] = v1 - v2;
        }
        __syncthreads();
#pragma unroll
        for (int i = 0; i < 4; i++) {
            int nl = ty + i * 8;
            size_t o = (size_t)(nb + nl) * HM + kb + tx;
            __nv_bfloat16 h, l;
            bf16split(ts[tx][nl], h, l); g_Bsh[o] = h; g_Bsl[o] = l;
            bf16split(ta[tx][nl], h, l); g_Bah[o] = h; g_Bal[o] = l;
        }
    }
}

// fold tmpF columns -> As/Aa bf16 splits
__global__ void fold_kernel() {
    int idx = blockIdx.x * 256 + threadIdx.x;   // [0, 2048*1024)
    int m = idx >> 10;
    int j = idx & (HM - 1);
    float a = g_tmpF[(size_t)m * MM + j];
    float c = g_tmpF[(size_t)m * MM + (MM - 1 - j)];
    size_t o = (size_t)m * HM + j;
    __nv_bfloat16 h, l;
    bf16split(a + c, h, l); g_Ash[o] = h; g_Asl[o] = l;
    bf16split(a - c, h, l); g_Aah[o] = h; g_Aal[o] = l;
}

// ------------------------- HMMA GEMM (K=1024, 128x128) ---------------------
#define KC      64
#define NCH2    (HM / KC)          // 16
#define T_A     16384              // one split tile: 128 rows x 128 B
#define ST_SZ   (4 * T_A)          // 64 KB
#define STAGES  3
#define SM_GEMM (STAGES * ST_SZ)   // 192 KB

__device__ __forceinline__ void load_chunk2(
    uint32_t st,
    const __nv_bfloat16* __restrict__ Ah, const __nv_bfloat16* __restrict__ Al,
    const __nv_bfloat16* __restrict__ Bh, const __nv_bfloat16* __restrict__ Bl,
    int m0, int n0, int k0, int tid)
{
#pragma unroll
    for (int t = 0; t < 16; ++t) {
        int idx  = tid + t * 256;
        int tile = idx >> 10;              // 0:Ah 1:Al 2:Bh 3:Bl
        int r    = (idx >> 3) & 127;
        int seg  = idx & 7;
        const __nv_bfloat16* src;
        int rb;
        if      (tile == 0) { src = Ah; rb = m0; }
        else if (tile == 1) { src = Al; rb = m0; }
        else if (tile == 2) { src = Bh; rb = n0; }
        else                { src = Bl; rb = n0; }
        cp16(st + tile * T_A + sw128(r * 128 + seg * 16),
             src + (size_t)(rb + r) * HM + k0 + seg * 8);
    }
}

// EPI 1: out fp32 tmpF rows 2*row+par (cols contiguous -> float2 store)
// EPI 2: out fp32 pad (row+PADB, PADB + 2*col + par)
template <int EPI>
__global__ __launch_bounds__(256, 1) void gemm_sym_kernel(
    const __nv_bfloat16* __restrict__ Ah0, const __nv_bfloat16* __restrict__ Al0,
    const __nv_bfloat16* __restrict__ Bh0, const __nv_bfloat16* __restrict__ Bl0,
    const __nv_bfloat16* __restrict__ Ah1, const __nv_bfloat16* __restrict__ Al1,
    const __nv_bfloat16* __restrict__ Bh1, const __nv_bfloat16* __restrict__ Bl1,
    float* __restrict__ out)
{
    extern __shared__ char smem[];
    uint32_t sb = smem_u32(smem);
    int tid = threadIdx.x, wid = tid >> 5, lane = tid & 31;
    int m0 = blockIdx.y * 128, n0 = blockIdx.x * 128;
    int par = blockIdx.z;
    int wm = wid & 1, wn = wid >> 1;       // 2(m) x 4(n), warp tile 64x32

    const __nv_bfloat16* Ah = par ? Ah1 : Ah0;
    const __nv_bfloat16* Al = par ? Al1 : Al0;
    const __nv_bfloat16* Bh = par ? Bh1 : Bh0;
    const __nv_bfloat16* Bl = par ? Bl1 : Bl0;

    float acc[4][4][4];
#pragma unroll
    for (int i = 0; i < 4; i++)
#pragma unroll
        for (int j = 0; j < 4; j++)
#pragma unroll
            for (int q = 0; q < 4; q++) acc[i][j][q] = 0.0f;

    int aRow  = wm * 64 + (lane & 7) + ((lane >> 3) & 1) * 8;
    int aSegB = lane >> 4;
    uint32_t aXor  = (uint32_t)(aRow & 7) << 4;
    uint32_t aBase = (uint32_t)aRow * 128;
    int bRow  = wn * 32 + (lane & 7) + ((lane >> 4) & 1) * 8;
    int bSegB = (lane >> 3) & 1;
    uint32_t bXor  = (uint32_t)(bRow & 7) << 4;
    uint32_t bBase = (uint32_t)bRow * 128;

    load_chunk2(sb + 0 * ST_SZ, Ah, Al, Bh, Bl, m0, n0, 0 * KC, tid); CP_COMMIT();
    load_chunk2(sb + 1 * ST_SZ, Ah, Al, Bh, Bl, m0, n0, 1 * KC, tid); CP_COMMIT();
    load_chunk2(sb + 2 * ST_SZ, Ah, Al, Bh, Bl, m0, n0, 2 * KC, tid); CP_COMMIT();

    for (int c = 0; c < NCH2; ++c) {
        if      (c <= NCH2 - 3) CP_WAIT(2);
        else if (c == NCH2 - 2) CP_WAIT(1);
        else                    CP_WAIT(0);
        __syncthreads();

        uint32_t st = sb + (c % STAGES) * ST_SZ;
        uint32_t sAh = st, sAl = st + T_A, sBh = st + 2 * T_A, sBl = st + 3 * T_A;

#pragma unroll
        for (int ks = 0; ks < 4; ++ks) {
            uint32_t ah[4][4], al[4][4], bh[2][4], bl[2][4];
            uint32_t aSegOff = (uint32_t)(((ks * 2 + aSegB) * 16) ^ aXor);
            uint32_t bSegOff = (uint32_t)(((ks * 2 + bSegB) * 16) ^ bXor);
#pragma unroll
            for (int mt = 0; mt < 4; ++mt) {
                uint32_t off = aBase + mt * 2048 + aSegOff;
                ldsm4(ah[mt][0], ah[mt][1], ah[mt][2], ah[mt][3], sAh + off);
                ldsm4(al[mt][0], al[mt][1], al[mt][2], al[mt][3], sAl + off);
            }
#pragma unroll
            for (int p = 0; p < 2; ++p) {
                uint32_t off = bBase + p * 2048 + bSegOff;
                ldsm4(bh[p][0], bh[p][1], bh[p][2], bh[p][3], sBh + off);
                ldsm4(bl[p][0], bl[p][1], bl[p][2], bl[p][3], sBl + off);
            }
#pragma unroll
            for (int mt = 0; mt < 4; ++mt)
#pragma unroll
                for (int nt = 0; nt < 4; ++nt) {
                    const uint32_t* pbh = &bh[nt >> 1][(nt & 1) * 2];
                    const uint32_t* pbl = &bl[nt >> 1][(nt & 1) * 2];
                    mma16816(acc[mt][nt], ah[mt], pbh);
                    mma16816(acc[mt][nt], ah[mt], pbl);
                    mma16816(acc[mt][nt], al[mt], pbh);
                }
        }
        __syncthreads();
        if (c + STAGES < NCH2) {
            load_chunk2(sb + (c % STAGES) * ST_SZ, Ah, Al, Bh, Bl,
                        m0, n0, (c + STAGES) * KC, tid);
            CP_COMMIT();
        } else {
            CP_COMMIT();
        }
    }

#pragma unroll
    for (int mt = 0; mt < 4; ++mt)
#pragma unroll
        for (int nt = 0; nt < 4; ++nt) {
#pragma unroll
            for (int h = 0; h < 2; ++h) {
                int row = m0 + wm * 64 + mt * 16 + (lane >> 2) + h * 8;
                int col = n0 + wn * 32 + nt * 8 + (lane & 3) * 2;
                float v0 = acc[mt][nt][h * 2 + 0];
                float v1 = acc[mt][nt][h * 2 + 1];
                if (EPI == 1) {
                    float2 st2; st2.x = v0; st2.y = v1;
                    *(float2*)&out[(size_t)(2 * row + par) * MM + col] = st2;
                } else {
                    size_t o = (size_t)(row + PADB) * PPS + PADB + 2 * col + par;
                    out[o]     = v0;
                    out[o + 2] = v1;
                }
            }
        }
}

// ------------------------------ tiled radon --------------------------------
#define RSW 100
#define RSH 95
#define RMAGIC 12582912.0f       // 1.5 * 2^23
#define RMAGIC_I 0x4B400000

__device__ __forceinline__ float radon_sample(
    const float* __restrict__ sm, int base0, float txm, float tym)
{
    float ux = txm + RMAGIC;
    float uy = tym + RMAGIC;
    int   nx = __float_as_int(ux) - RMAGIC_I;
    int   ny = __float_as_int(uy) - RMAGIC_I;
    float wx = (txm - (ux - RMAGIC)) + 0.5f;
    float wy = (tym - (uy - RMAGIC)) + 0.5f;
    const float* p = sm + (base0 + ny * RSW + nx);
    float s00 = p[0], s01 = p[1], s10 = p[RSW], s11 = p[RSW + 1];
    float top = fmaf(wx, s01 - s00, s00);
    float bot = fmaf(wx, s11 - s10, s10);
    return fmaf(wy, bot - top, top);
}

__global__ __launch_bounds__(256) void radon_tiled_kernel() {
    __shared__ float sm[RSH * RSW];
    __shared__ float red[256];

    int a  = blockIdx.z;
    int x0 = blockIdx.x * 64;
    int y0 = blockIdx.y * 64;
    int tid = threadIdx.x, wid = tid >> 5, lane = tid & 31;

    float ang = (float)(3.141592653589793 * (double)a / 31.0);
    float ca = cosf(ang);
    float sa = sinf(ang);
    const float cen = (float)(PP / 2);
    float c1 = cen * (ca + sa - 1.0f);
    float c2 = cen * (ca - sa - 1.0f);

    float xf0 = (float)x0, xf1 = (float)(x0 + 63);
    float yf0 = (float)y0, yf1 = (float)(y0 + 63);
    float u00 = ca * xf0 + sa * yf0 - c1, u01 = ca * xf0 + sa * yf1 - c1;
    float u10 = ca * xf1 + sa * yf0 - c1, u11 = ca * xf1 + sa * yf1 - c1;
    float v00 = -sa * xf0 + ca * yf0 - c2, v01 = -sa * xf0 + ca * yf1 - c2;
    float v10 = -sa * xf1 + ca * yf0 - c2, v11 = -sa * xf1 + ca * yf1 - c2;
    float umin = fminf(fminf(u00, u01), fminf(u10, u11));
    float umax = fmaxf(fmaxf(u00, u01), fmaxf(u10, u11));
    float vmin = fminf(fminf(v00, v01), fminf(v10, v11));
    float vmax = fmaxf(fmaxf(v00, v01), fmaxf(v10, v11));

    int u0i = (int)floorf(umin) - 1;
    int v0i = (int)floorf(vmin) - 1;
    int W = (int)floorf(umax) + 2 - u0i + 1;
    int H = (int)floorf(vmax) + 2 - v0i + 1;

    int u0m = u0i % PP; if (u0m < 0) u0m += PP;
    int v0m = v0i % PP; if (v0m < 0) v0m += PP;

    int sft  = u0m & 3;
    int u0s  = u0i - sft;
    int u0ms = u0m - sft;
    int W4   = (W + sft + 3) & ~3;

    uint32_t smb = smem_u32(sm);
    if (u0ms + W4 <= PP) {
        int nq = W4 >> 2;
        for (int r = wid; r < H; r += 8) {
            int rm = v0m + r; if (rm >= PP) rm -= PP;
            const float* src = g_pad + (size_t)rm * PPS + u0ms;
            uint32_t drow = smb + (uint32_t)(r * RSW) * 4;
            for (int q = lane; q < nq; q += 32)
                cp16(drow + (uint32_t)q * 16, src + q * 4);
        }
    } else {
        for (int r = wid; r < H; r += 8) {
            int rm = v0m + r; if (rm >= PP) rm -= PP;
            const float* rowp = g_pad + (size_t)rm * PPS;
            uint32_t drow = smb + (uint32_t)(r * RSW) * 4;
            for (int c = lane; c < W4; c += 32) {
                int cm = u0ms + c; if (cm >= PP) cm -= PP;
                cp4(drow + (uint32_t)c * 4, rowp + cm);
            }
        }
    }
    CP_COMMIT();

    int xl   = tid & 63;
    int ysub = tid >> 6;
    int x    = x0 + xl;
    float xf = (float)x;
    float bx = ca * xf - c1;
    float by = -sa * xf - c2;

    int ybeg = y0 + ysub * 16;
    float ybf  = (float)ybeg;
    float xin0 = fmaf(sa, ybf, bx);
    float yin0 = fmaf(ca, ybf, by);
    float fx0 = floorf(xin0);
    float fy0 = floorf(yin0);
    float wx0m = (xin0 - fx0) - 0.5f;
    float wy0m = (yin0 - fy0) - 0.5f;
    int   base0 = ((int)fy0 - v0i) * RSW + ((int)fx0 - u0s);

    CP_WAIT(0);
    __syncthreads();

    float acc0 = 0.0f, acc1 = 0.0f;
    if (y0 + 64 <= PP) {
#pragma unroll
        for (int i = 0; i < 16; ++i) {
            float r = radon_sample(sm, base0,
                                   fmaf((float)i, sa, wx0m),
                                   fmaf((float)i, ca, wy0m));
            if (i & 1) acc1 += r; else acc0 += r;
        }
    } else {
#pragma unroll
        for (int i = 0; i < 16; ++i) {
            float r = radon_sample(sm, base0,
                                   fmaf((float)i, sa, wx0m),
                                   fmaf((float)i, ca, wy0m));
            float g = (ybeg + i < PP) ? 1.0f : 0.0f;
            if (i & 1) acc1 = fmaf(g, r, acc1);
            else       acc0 = fmaf(g, r, acc0);
        }
    }
    float acc = acc0 + acc1;

    __syncthreads();
    red[ysub * 64 + xl] = acc;
    __syncthreads();
    if (tid < 64) {
        float s = ((red[tid] + red[64 + tid]) + red[128 + tid]) + red[192 + tid];
        int xo = x0 + tid;
        if (xo < PP)
            g_lpart[(size_t)blockIdx.y * TOT + a * PP + xo] = s;
    }
}

// --------------------------- reduce / normalize ----------------------------
__global__ void reduce_max_kernel() {
    __shared__ float smax[256];
    int idx = blockIdx.x * 256 + threadIdx.x;
    float v = -__int_as_float(0x7f800000);
    if (idx < TOT) {
        float s = 0.0f;
        for (int p = 0; p < NYT; p++) s += g_lpart[(size_t)p * TOT + idx];
        g_lines[idx] = s;
        v = s;
    }
    smax[threadIdx.x] = v;
    __syncthreads();
    for (int o = 128; o > 0; o >>= 1) {
        if (threadIdx.x < o)
            smax[threadIdx.x] = fmaxf(smax[threadIdx.x], smax[threadIdx.x + o]);
        __syncthreads();
    }
    if (threadIdx.x == 0) {
        unsigned u = __float_as_uint(smax[0]);
        unsigned enc = (u & 0x80000000u) ? ~u : (u | 0x80000000u);
        atomicMax(&g_maxbits, enc);
    }
}

__global__ void normalize_kernel(float* __restrict__ out) {
    int idx = blockIdx.x * 256 + threadIdx.x;
    if (idx >= TOT) return;
    unsigned u = g_maxbits;
    float mx = (u & 0x80000000u) ? __uint_as_float(u & 0x7fffffffu)
                                 : __uint_as_float(~u);
    int x = idx >> 5;
    int a = idx & 31;
    out[idx] = g_lines[a * PP + x] / mx;
}

// ---------------------------------------------------------------------------
extern "C" void kernel_launch(void* const* d_in, const int* in_sizes, int n_in,
                              void* d_out, int out_size) {
    const float* img = (const float*)d_in[0];
    float* out = (float*)d_out;

    static int s_init = 0;
    if (!s_init) {
        cudaFuncSetAttribute(gemm_sym_kernel<1>,
                             cudaFuncAttributeMaxDynamicSharedMemorySize, SM_GEMM);
        cudaFuncSetAttribute(gemm_sym_kernel<2>,
                             cudaFuncAttributeMaxDynamicSharedMemorySize, SM_GEMM);
        s_init = 1;
    }

    prep_kernel<<<NBB + NCG + NTS, 256>>>(img);

    __nv_bfloat16 *pCeh, *pCel, *pCoh, *pCol;
    __nv_bfloat16 *pBsh, *pBsl, *pBah, *pBal;
    __nv_bfloat16 *pAsh, *pAsl, *pAah, *pAal;
    float *pTmpF, *pPad;
    cudaGetSymbolAddress((void**)&pCeh, g_Ceh);
    cudaGetSymbolAddress((void**)&pCel, g_Cel);
    cudaGetSymbolAddress((void**)&pCoh, g_Coh);
    cudaGetSymbolAddress((void**)&pCol, g_Col);
    cudaGetSymbolAddress((void**)&pBsh, g_Bsh);
    cudaGetSymbolAddress((void**)&pBsl, g_Bsl);
    cudaGetSymbolAddress((void**)&pBah, g_Bah);
    cudaGetSymbolAddress((void**)&pBal, g_Bal);
    cudaGetSymbolAddress((void**)&pAsh, g_Ash);
    cudaGetSymbolAddress((void**)&pAsl, g_Asl);
    cudaGetSymbolAddress((void**)&pAah, g_Aah);
    cudaGetSymbolAddress((void**)&pAal, g_Aal);
    cudaGetSymbolAddress((void**)&pTmpF, g_tmpF);
    cudaGetSymbolAddress((void**)&pPad, g_pad);

    // gemm1: tmp[2m'+p, n] = (p? Co:Ce) . (p? Ba:Bs)^T ; M=1024, N=2048
    dim3 g1(MM / 128, HM / 128, 2);
    gemm_sym_kernel<1><<<g1, 256, SM_GEMM>>>(pCeh, pCel, pBsh, pBsl,
                                             pCoh, pCol, pBah, pBal, pTmpF);
    fold_kernel<<<MM * HM / 256, 256>>>();

    // gemm2: pad[m+PADB, PADB+2n'+p] = (p? Aa:As) . (p? Co:Ce)^T ; M=2048, N=1024
    dim3 g2(HM / 128, MM / 128, 2);
    gemm_sym_kernel<2><<<g2, 256, SM_GEMM>>>(pAsh, pAsl, pCeh, pCel,
                                             pAah, pAal, pCoh, pCol, pPad);

    dim3 rg(NXT, NYT, NANG);
    radon_tiled_kernel<<<rg, 256>>>();

    reduce_max_kernel<<<(TOT + 255) / 256, 256>>>();
    normalize_kernel<<<(TOT + 255) / 256, 256>>>(out);
}

// round 13
// speedup vs baseline: 1.3626x; 1.0145x over previous
#include <cuda_runtime.h>
#include <cuda_bf16.h>
#include <cstdint>

// ---------------------------------------------------------------------------
// image_prj: D = dct2(image) [2048x2048, ortho] -> pad to 2198x2198 ->
// 32-angle radon (bilinear, WRAP) -> lines^T / max
// GEMMs: DCT even/odd fold (half FLOPs); gemm1 computes mirror column pairs
// and emits folded A operands directly (no tmp/fold pass). Radon: cp.async
// tile + bias-round bilinear with IMAD-on-bits addressing.
// ---------------------------------------------------------------------------

#define MM    2048
#define HM    1024
#define PP    2198
#define PPS   2200
#define PADB  75
#define NANG  32
#define TOT   (NANG * PP)
#define NYT   35
#define NXT   35

__device__ __nv_bfloat16 g_Ceh[HM * HM], g_Cel[HM * HM];   // C even rows
__device__ __nv_bfloat16 g_Coh[HM * HM], g_Col[HM * HM];   // C odd rows
__device__ __nv_bfloat16 g_Bsh[MM * HM], g_Bsl[MM * HM];   // X^T fold-sum
__device__ __nv_bfloat16 g_Bah[MM * HM], g_Bal[MM * HM];   // X^T fold-diff
__device__ __nv_bfloat16 g_Ash[MM * HM], g_Asl[MM * HM];   // tmp fold-sum
__device__ __nv_bfloat16 g_Aah[MM * HM], g_Aal[MM * HM];   // tmp fold-diff
__device__ float    g_pad[PP * PPS];
__device__ float    g_lpart[NYT * TOT];
__device__ float    g_lines[TOT];
__device__ unsigned g_maxbits;

// ------------------------------ PTX helpers -------------------------------
__device__ __forceinline__ uint32_t smem_u32(const void* p) {
    uint32_t a;
    asm("{ .reg .u64 t; cvta.to.shared.u64 t, %1; cvt.u32.u64 %0, t; }"
        : "=r"(a) : "l"(p));
    return a;
}
#define CP_COMMIT() asm volatile("cp.async.commit_group;" ::: "memory")
#define CP_WAIT(n)  asm volatile("cp.async.wait_group %0;" :: "n"(n) : "memory")

__device__ __forceinline__ void cp16(uint32_t dst, const void* src) {
    asm volatile("cp.async.cg.shared.global [%0], [%1], 16;"
                 :: "r"(dst), "l"(src) : "memory");
}
__device__ __forceinline__ void cp4(uint32_t dst, const void* src) {
    asm volatile("cp.async.ca.shared.global [%0], [%1], 4;"
                 :: "r"(dst), "l"(src) : "memory");
}
__device__ __forceinline__ void ldsm4(uint32_t& r0, uint32_t& r1,
                                      uint32_t& r2, uint32_t& r3, uint32_t a) {
    asm volatile("ldmatrix.sync.aligned.m8n8.x4.shared.b16 {%0,%1,%2,%3}, [%4];"
                 : "=r"(r0), "=r"(r1), "=r"(r2), "=r"(r3) : "r"(a));
}
__device__ __forceinline__ void mma16816(float* d, const uint32_t* a,
                                         const uint32_t* b) {
    asm volatile("mma.sync.aligned.m16n8k16.row.col.f32.bf16.bf16.f32 "
                 "{%0,%1,%2,%3}, {%4,%5,%6,%7}, {%8,%9}, {%0,%1,%2,%3};"
                 : "+f"(d[0]), "+f"(d[1]), "+f"(d[2]), "+f"(d[3])
                 : "r"(a[0]), "r"(a[1]), "r"(a[2]), "r"(a[3]),
                   "r"(b[0]), "r"(b[1]));
}
__device__ __forceinline__ uint32_t sw128(uint32_t b) { return b ^ ((b >> 3) & 0x70); }
__device__ __forceinline__ void bf16split(float v, __nv_bfloat16& h, __nv_bfloat16& l) {
    h = __float2bfloat16(v);
    l = __float2bfloat16(v - __bfloat162float(h));
}

// --------------------------- merged prep kernel ----------------------------
#define NB1 (150 * PP)
#define NB2 (MM * 150)
#define NBB ((NB1 + NB2 + 255) / 256)
#define NCG (2 * HM * HM / 256)
#define NTS ((HM / 32) * (MM / 32))

__global__ void prep_kernel(const float* __restrict__ img) {
    __shared__ float ts[32][33];
    __shared__ float ta[32][33];
    int b = blockIdx.x;
    int tid = threadIdx.x;

    if (b < NBB) {
        int idx = b * 256 + tid;
        if (idx == 0) g_maxbits = 0u;
        if (idx < NB1) {
            int r = idx / PP, c = idx % PP;
            int row = (r < 75) ? r : (2123 + r - 75);
            g_pad[(size_t)row * PPS + c] = 0.0f;
        } else if (idx < NB1 + NB2) {
            int j = idx - NB1;
            int r = j / 150, c = j % 150;
            int col = (c < 75) ? c : (2123 + c - 75);
            g_pad[(size_t)(75 + r) * PPS + col] = 0.0f;
        }
        return;
    }
    b -= NBB;
    if (b < NCG) {
        int idx = b * 256 + tid;
        int par = idx >> 20;
        int mp  = (idx >> 10) & (HM - 1);
        int n   = idx & (HM - 1);
        int k   = 2 * mp + par;
        int r   = ((2 * n + 1) * k) & (4 * MM - 1);
        float t = (float)r * (1.0f / (2.0f * MM));
        float c = cospif(t);
        float s = (k == 0) ? 0.022097086912079608f : 0.03125f;
        float v = s * c;
        __nv_bfloat16 h, l; bf16split(v, h, l);
        size_t o = (size_t)mp * HM + n;
        if (par) { g_Coh[o] = h; g_Col[o] = l; }
        else     { g_Ceh[o] = h; g_Cel[o] = l; }
        return;
    }
    b -= NCG;
    {
        int kt = b & 31, nt = b >> 5;
        int kb = kt * 32, nb = nt * 32;
        int tx = tid & 31, ty = tid >> 5;
#pragma unroll
        for (int i = 0; i < 4; i++) {
            int k = kb + ty + i * 8;
            float v1 = img[(size_t)k * MM + nb + tx];
            float v2 = img[(size_t)(MM - 1 - k) * MM + nb + tx];
            ts[ty + i * 8][tx] = v1 + v2;
            ta[ty + i * 8][tx] = v1 - v2;
        }
        __syncthreads();
#pragma unroll
        for (int i = 0; i < 4; i++) {
            int nl = ty + i * 8;
            size_t o = (size_t)(nb + nl) * HM + kb + tx;
            __nv_bfloat16 h, l;
            bf16split(ts[tx][nl], h, l); g_Bsh[o] = h; g_Bsl[o] = l;
            bf16split(ta[tx][nl], h, l); g_Bah[o] = h; g_Bal[o] = l;
        }
    }
}

// --------------------- gemm1: mirror-pair, fold-emitting --------------------
// tmp[2m'+p, j]   = sum_k Cp[m',k] Bp[j,k]        (j tile)
// tmp[2m'+p, j~]  with j~ = 2047-j                (mirror tile, reversed rows)
// emits As/Aa[2m'+p, j] = tmp_j +/- tmp_j~ as bf16 hi/lo. K=1024.
#define KC      64
#define NCH2    (HM / KC)          // 16
#define T_T     16384              // one 128-row split tile (128 x 128B)
#define ST1_SZ  (6 * T_T)          // Ah,Al,B0h,B0l,B1h,B1l = 96KB
#define SM_G1   (2 * ST1_SZ)       // 192KB

__device__ __forceinline__ void g1_load_chunk(
    uint32_t st,
    const __nv_bfloat16* __restrict__ Ah, const __nv_bfloat16* __restrict__ Al,
    const __nv_bfloat16* __restrict__ Bh, const __nv_bfloat16* __restrict__ Bl,
    int m0, int n0, int k0, int tid)
{
#pragma unroll
    for (int t = 0; t < 24; ++t) {
        int idx  = tid + t * 256;          // 6144 x 16B
        int tile = idx >> 10;              // 0:Ah 1:Al 2:B0h 3:B0l 4:B1h 5:B1l
        int r    = (idx >> 3) & 127;
        int seg  = idx & 7;
        const __nv_bfloat16* src;
        int row;
        switch (tile) {
            case 0: src = Ah; row = m0 + r; break;
            case 1: src = Al; row = m0 + r; break;
            case 2: src = Bh; row = n0 + r; break;
            case 3: src = Bl; row = n0 + r; break;
            case 4: src = Bh; row = MM - 1 - n0 - r; break;   // mirror, reversed
            default: src = Bl; row = MM - 1 - n0 - r; break;
        }
        cp16(st + tile * T_T + sw128(r * 128 + seg * 16),
             src + (size_t)row * HM + k0 + seg * 8);
    }
}

__global__ __launch_bounds__(256, 1) void gemm1_kernel(
    const __nv_bfloat16* __restrict__ Ah0, const __nv_bfloat16* __restrict__ Al0,
    const __nv_bfloat16* __restrict__ Ah1, const __nv_bfloat16* __restrict__ Al1)
{
    extern __shared__ char smem[];
    uint32_t sb = smem_u32(smem);
    int tid = threadIdx.x, wid = tid >> 5, lane = tid & 31;
    int m0 = blockIdx.y * 128, n0 = blockIdx.x * 128;
    int par = blockIdx.z;
    int wm = wid & 1, wn = wid >> 1;       // 2(m) x 4(n), warp tile 64x32

    const __nv_bfloat16* Ah = par ? Ah1 : Ah0;
    const __nv_bfloat16* Al = par ? Al1 : Al0;
    const __nv_bfloat16* Bh = par ? g_Bah : g_Bsh;
    const __nv_bfloat16* Bl = par ? g_Bal : g_Bsl;

    float acc0[4][4][4], acc1[4][4][4];
#pragma unroll
    for (int i = 0; i < 4; i++)
#pragma unroll
        for (int j = 0; j < 4; j++)
#pragma unroll
            for (int q = 0; q < 4; q++) { acc0[i][j][q] = 0.0f; acc1[i][j][q] = 0.0f; }

    int aRow  = wm * 64 + (lane & 7) + ((lane >> 3) & 1) * 8;
    int aSegB = lane >> 4;
    uint32_t aXor  = (uint32_t)(aRow & 7) << 4;
    uint32_t aBase = (uint32_t)aRow * 128;
    int bRow  = wn * 32 + (lane & 7) + ((lane >> 4) & 1) * 8;
    int bSegB = (lane >> 3) & 1;
    uint32_t bXor  = (uint32_t)(bRow & 7) << 4;
    uint32_t bBase = (uint32_t)bRow * 128;

    g1_load_chunk(sb + 0 * ST1_SZ, Ah, Al, Bh, Bl, m0, n0, 0 * KC, tid); CP_COMMIT();
    g1_load_chunk(sb + 1 * ST1_SZ, Ah, Al, Bh, Bl, m0, n0, 1 * KC, tid); CP_COMMIT();

    for (int c = 0; c < NCH2; ++c) {
        if (c + 1 < NCH2) CP_WAIT(1);
        else              CP_WAIT(0);
        __syncthreads();

        uint32_t st = sb + (c & 1) * ST1_SZ;
        uint32_t sAh = st, sAl = st + T_T;
        uint32_t sB0h = st + 2 * T_T, sB0l = st + 3 * T_T;
        uint32_t sB1h = st + 4 * T_T, sB1l = st + 5 * T_T;

#pragma unroll
        for (int ks = 0; ks < 4; ++ks) {
            uint32_t aSegOff = (uint32_t)(((ks * 2 + aSegB) * 16) ^ aXor);
            uint32_t bSegOff = (uint32_t)(((ks * 2 + bSegB) * 16) ^ bXor);
            uint32_t b0h[2][4], b0l[2][4], b1h[2][4], b1l[2][4];
#pragma unroll
            for (int p = 0; p < 2; ++p) {
                uint32_t off = bBase + p * 2048 + bSegOff;
                ldsm4(b0h[p][0], b0h[p][1], b0h[p][2], b0h[p][3], sB0h + off);
                ldsm4(b0l[p][0], b0l[p][1], b0l[p][2], b0l[p][3], sB0l + off);
                ldsm4(b1h[p][0], b1h[p][1], b1h[p][2], b1h[p][3], sB1h + off);
                ldsm4(b1l[p][0], b1l[p][1], b1l[p][2], b1l[p][3], sB1l + off);
            }
#pragma unroll
            for (int mt = 0; mt < 4; ++mt) {
                uint32_t ah[4], al[4];
                uint32_t off = aBase + mt * 2048 + aSegOff;
                ldsm4(ah[0], ah[1], ah[2], ah[3], sAh + off);
                ldsm4(al[0], al[1], al[2], al[3], sAl + off);
#pragma unroll
                for (int nt = 0; nt < 4; ++nt) {
                    const uint32_t* p0h = &b0h[nt >> 1][(nt & 1) * 2];
                    const uint32_t* p0l = &b0l[nt >> 1][(nt & 1) * 2];
                    const uint32_t* p1h = &b1h[nt >> 1][(nt & 1) * 2];
                    const uint32_t* p1l = &b1l[nt >> 1][(nt & 1) * 2];
                    mma16816(acc0[mt][nt], ah, p0h);
                    mma16816(acc0[mt][nt], ah, p0l);
                    mma16816(acc0[mt][nt], al, p0h);
                    mma16816(acc1[mt][nt], ah, p1h);
                    mma16816(acc1[mt][nt], ah, p1l);
                    mma16816(acc1[mt][nt], al, p1h);
                }
            }
        }
        __syncthreads();
        if (c + 2 < NCH2) {
            g1_load_chunk(sb + (c & 1) * ST1_SZ, Ah, Al, Bh, Bl,
                          m0, n0, (c + 2) * KC, tid);
        }
        CP_COMMIT();
    }

    // epilogue: As/Aa[2*row+par, col] from (tile0 +/- mirror tile1)
#pragma unroll
    for (int mt = 0; mt < 4; ++mt)
#pragma unroll
        for (int nt = 0; nt < 4; ++nt) {
#pragma unroll
            for (int h = 0; h < 2; ++h) {
                int row = m0 + wm * 64 + mt * 16 + (lane >> 2) + h * 8;
                int col = n0 + wn * 32 + nt * 8 + (lane & 3) * 2;
                float v0 = acc0[mt][nt][h * 2 + 0];
                float v1 = acc0[mt][nt][h * 2 + 1];
                float u0 = acc1[mt][nt][h * 2 + 0];
                float u1 = acc1[mt][nt][h * 2 + 1];
                size_t o = (size_t)(2 * row + par) * HM + col;
                __nv_bfloat16 h0, l0, h1, l1;
                bf16split(v0 + u0, h0, l0); bf16split(v1 + u1, h1, l1);
                __nv_bfloat162 hp, lp;
                hp.x = h0; hp.y = h1; lp.x = l0; lp.y = l1;
                *(__nv_bfloat162*)&g_Ash[o] = hp;
                *(__nv_bfloat162*)&g_Asl[o] = lp;
                bf16split(v0 - u0, h0, l0); bf16split(v1 - u1, h1, l1);
                hp.x = h0; hp.y = h1; lp.x = l0; lp.y = l1;
                *(__nv_bfloat162*)&g_Aah[o] = hp;
                *(__nv_bfloat162*)&g_Aal[o] = lp;
            }
        }
}

// ------------------------- gemm2 (unchanged, K=1024) -----------------------
#define ST_SZ   (4 * T_T)          // 64 KB
#define STAGES  3
#define SM_G2   (STAGES * ST_SZ)   // 192 KB

__device__ __forceinline__ void g2_load_chunk(
    uint32_t st,
    const __nv_bfloat16* __restrict__ Ah, const __nv_bfloat16* __restrict__ Al,
    const __nv_bfloat16* __restrict__ Bh, const __nv_bfloat16* __restrict__ Bl,
    int m0, int n0, int k0, int tid)
{
#pragma unroll
    for (int t = 0; t < 16; ++t) {
        int idx  = tid + t * 256;
        int tile = idx >> 10;
        int r    = (idx >> 3) & 127;
        int seg  = idx & 7;
        const __nv_bfloat16* src;
        int rb;
        if      (tile == 0) { src = Ah; rb = m0; }
        else if (tile == 1) { src = Al; rb = m0; }
        else if (tile == 2) { src = Bh; rb = n0; }
        else                { src = Bl; rb = n0; }
        cp16(st + tile * T_T + sw128(r * 128 + seg * 16),
             src + (size_t)(rb + r) * HM + k0 + seg * 8);
    }
}

__global__ __launch_bounds__(256, 1) void gemm2_kernel(
    const __nv_bfloat16* __restrict__ Bh0, const __nv_bfloat16* __restrict__ Bl0,
    const __nv_bfloat16* __restrict__ Bh1, const __nv_bfloat16* __restrict__ Bl1)
{
    extern __shared__ char smem[];
    uint32_t sb = smem_u32(smem);
    int tid = threadIdx.x, wid = tid >> 5, lane = tid & 31;
    int m0 = blockIdx.y * 128, n0 = blockIdx.x * 128;
    int par = blockIdx.z;
    int wm = wid & 1, wn = wid >> 1;

    const __nv_bfloat16* Ah = par ? g_Aah : g_Ash;
    const __nv_bfloat16* Al = par ? g_Aal : g_Asl;
    const __nv_bfloat16* Bh = par ? Bh1 : Bh0;
    const __nv_bfloat16* Bl = par ? Bl1 : Bl0;

    float acc[4][4][4];
#pragma unroll
    for (int i = 0; i < 4; i++)
#pragma unroll
        for (int j = 0; j < 4; j++)
#pragma unroll
            for (int q = 0; q < 4; q++) acc[i][j][q] = 0.0f;

    int aRow  = wm * 64 + (lane & 7) + ((lane >> 3) & 1) * 8;
    int aSegB = lane >> 4;
    uint32_t aXor  = (uint32_t)(aRow & 7) << 4;
    uint32_t aBase = (uint32_t)aRow * 128;
    int bRow  = wn * 32 + (lane & 7) + ((lane >> 4) & 1) * 8;
    int bSegB = (lane >> 3) & 1;
    uint32_t bXor  = (uint32_t)(bRow & 7) << 4;
    uint32_t bBase = (uint32_t)bRow * 128;

    g2_load_chunk(sb + 0 * ST_SZ, Ah, Al, Bh, Bl, m0, n0, 0 * KC, tid); CP_COMMIT();
    g2_load_chunk(sb + 1 * ST_SZ, Ah, Al, Bh, Bl, m0, n0, 1 * KC, tid); CP_COMMIT();
    g2_load_chunk(sb + 2 * ST_SZ, Ah, Al, Bh, Bl, m0, n0, 2 * KC, tid); CP_COMMIT();

    for (int c = 0; c < NCH2; ++c) {
        if      (c <= NCH2 - 3) CP_WAIT(2);
        else if (c == NCH2 - 2) CP_WAIT(1);
        else                    CP_WAIT(0);
        __syncthreads();

        uint32_t st = sb + (c % STAGES) * ST_SZ;
        uint32_t sAh = st, sAl = st + T_T, sBh = st + 2 * T_T, sBl = st + 3 * T_T;

#pragma unroll
        for (int ks = 0; ks < 4; ++ks) {
            uint32_t ah[4][4], al[4][4], bh[2][4], bl[2][4];
            uint32_t aSegOff = (uint32_t)(((ks * 2 + aSegB) * 16) ^ aXor);
            uint32_t bSegOff = (uint32_t)(((ks * 2 + bSegB) * 16) ^ bXor);
#pragma unroll
            for (int mt = 0; mt < 4; ++mt) {
                uint32_t off = aBase + mt * 2048 + aSegOff;
                ldsm4(ah[mt][0], ah[mt][1], ah[mt][2], ah[mt][3], sAh + off);
                ldsm4(al[mt][0], al[mt][1], al[mt][2], al[mt][3], sAl + off);
            }
#pragma unroll
            for (int p = 0; p < 2; ++p) {
                uint32_t off = bBase + p * 2048 + bSegOff;
                ldsm4(bh[p][0], bh[p][1], bh[p][2], bh[p][3], sBh + off);
                ldsm4(bl[p][0], bl[p][1], bl[p][2], bl[p][3], sBl + off);
            }
#pragma unroll
            for (int mt = 0; mt < 4; ++mt)
#pragma unroll
                for (int nt = 0; nt < 4; ++nt) {
                    const uint32_t* pbh = &bh[nt >> 1][(nt & 1) * 2];
                    const uint32_t* pbl = &bl[nt >> 1][(nt & 1) * 2];
                    mma16816(acc[mt][nt], ah[mt], pbh);
                    mma16816(acc[mt][nt], ah[mt], pbl);
                    mma16816(acc[mt][nt], al[mt], pbh);
                }
        }
        __syncthreads();
        if (c + STAGES < NCH2) {
            g2_load_chunk(sb + (c % STAGES) * ST_SZ, Ah, Al, Bh, Bl,
                          m0, n0, (c + STAGES) * KC, tid);
        }
        CP_COMMIT();
    }

#pragma unroll
    for (int mt = 0; mt < 4; ++mt)
#pragma unroll
        for (int nt = 0; nt < 4; ++nt) {
#pragma unroll
            for (int h = 0; h < 2; ++h) {
                int row = m0 + wm * 64 + mt * 16 + (lane >> 2) + h * 8;
                int col = n0 + wn * 32 + nt * 8 + (lane & 3) * 2;
                float v0 = acc[mt][nt][h * 2 + 0];
                float v1 = acc[mt][nt][h * 2 + 1];
                size_t o = (size_t)(row + PADB) * PPS + PADB + 2 * col + par;
                g_pad[o]     = v0;
                g_pad[o + 2] = v1;
            }
        }
}

// ------------------------------ tiled radon --------------------------------
#define RSW 100
#define RSH 95
#define RMAGIC 12582912.0f       // 1.5 * 2^23
#define RMAGIC_I 0x4B400000

// addr = smem byte base' + uybits*400 + uxbits*4 (mod 2^32); base' absorbs
// -MAGIC_I*404.  Pure IMAD addressing, no int subtracts.
__device__ __forceinline__ float radon_sample(
    uint32_t cbase, float txm, float tym)
{
    float ux = txm + RMAGIC;
    float uy = tym + RMAGIC;
    float wx = (txm - (ux - RMAGIC)) + 0.5f;
    float wy = (tym - (uy - RMAGIC)) + 0.5f;
    uint32_t addr = cbase + __float_as_uint(uy) * (RSW * 4u)
                          + __float_as_uint(ux) * 4u;
    float s00, s01, s10, s11;
    asm volatile("ld.shared.f32 %0, [%1];"       : "=f"(s00) : "r"(addr));
    asm volatile("ld.shared.f32 %0, [%1+4];"     : "=f"(s01) : "r"(addr));
    asm volatile("ld.shared.f32 %0, [%1+400];"   : "=f"(s10) : "r"(addr));
    asm volatile("ld.shared.f32 %0, [%1+404];"   : "=f"(s11) : "r"(addr));
    float top = fmaf(wx, s01 - s00, s00);
    float bot = fmaf(wx, s11 - s10, s10);
    return fmaf(wy, bot - top, top);
}

__global__ __launch_bounds__(256) void radon_tiled_kernel() {
    __shared__ float sm[RSH * RSW];
    __shared__ float red[256];

    int a  = blockIdx.z;
    int x0 = blockIdx.x * 64;
    int y0 = blockIdx.y * 64;
    int tid = threadIdx.x, wid = tid >> 5, lane = tid & 31;

    float ang = (float)(3.141592653589793 * (double)a / 31.0);
    float ca = cosf(ang);
    float sa = sinf(ang);
    const float cen = (float)(PP / 2);
    float c1 = cen * (ca + sa - 1.0f);
    float c2 = cen * (ca - sa - 1.0f);

    float xf0 = (float)x0, xf1 = (float)(x0 + 63);
    float yf0 = (float)y0, yf1 = (float)(y0 + 63);
    float u00 = ca * xf0 + sa * yf0 - c1, u01 = ca * xf0 + sa * yf1 - c1;
    float u10 = ca * xf1 + sa * yf0 - c1, u11 = ca * xf1 + sa * yf1 - c1;
    float v00 = -sa * xf0 + ca * yf0 - c2, v01 = -sa * xf0 + ca * yf1 - c2;
    float v10 = -sa * xf1 + ca * yf0 - c2, v11 = -sa * xf1 + ca * yf1 - c2;
    float umin = fminf(fminf(u00, u01), fminf(u10, u11));
    float umax = fmaxf(fmaxf(u00, u01), fmaxf(u10, u11));
    float vmin = fminf(fminf(v00, v01), fminf(v10, v11));
    float vmax = fmaxf(fmaxf(v00, v01), fmaxf(v10, v11));

    int u0i = (int)floorf(umin) - 1;
    int v0i = (int)floorf(vmin) - 1;
    int W = (int)floorf(umax) + 2 - u0i + 1;
    int H = (int)floorf(vmax) + 2 - v0i + 1;

    int u0m = u0i % PP; if (u0m < 0) u0m += PP;
    int v0m = v0i % PP; if (v0m < 0) v0m += PP;

    int sft  = u0m & 3;
    int u0s  = u0i - sft;
    int u0ms = u0m - sft;
    int W4   = (W + sft + 3) & ~3;

    uint32_t smb = smem_u32(sm);
    if (u0ms + W4 <= PP) {
        int nq = W4 >> 2;
        for (int r = wid; r < H; r += 8) {
            int rm = v0m + r; if (rm >= PP) rm -= PP;
            const float* src = g_pad + (size_t)rm * PPS + u0ms;
            uint32_t drow = smb + (uint32_t)(r * RSW) * 4;
            for (int q = lane; q < nq; q += 32)
                cp16(drow + (uint32_t)q * 16, src + q * 4);
        }
    } else {
        for (int r = wid; r < H; r += 8) {
            int rm = v0m + r; if (rm >= PP) rm -= PP;
            const float* rowp = g_pad + (size_t)rm * PPS;
            uint32_t drow = smb + (uint32_t)(r * RSW) * 4;
            for (int c = lane; c < W4; c += 32) {
                int cm = u0ms + c; if (cm >= PP) cm -= PP;
                cp4(drow + (uint32_t)c * 4, rowp + cm);
            }
        }
    }
    CP_COMMIT();

    int xl   = tid & 63;
    int ysub = tid >> 6;
    int x    = x0 + xl;
    float xf = (float)x;
    float bx = ca * xf - c1;
    float by = -sa * xf - c2;

    int ybeg = y0 + ysub * 16;
    float ybf  = (float)ybeg;
    float xin0 = fmaf(sa, ybf, bx);
    float yin0 = fmaf(ca, ybf, by);
    float fx0 = floorf(xin0);
    float fy0 = floorf(yin0);
    float wx0m = (xin0 - fx0) - 0.5f;
    float wy0m = (yin0 - fy0) - 0.5f;
    int   base0 = ((int)fy0 - v0i) * RSW + ((int)fx0 - u0s);
    // byte base with magic-bits folded out (mod 2^32 arithmetic)
    uint32_t cbase = smb + (uint32_t)base0 * 4u
                   - (uint32_t)RMAGIC_I * (RSW * 4u)
                   - (uint32_t)RMAGIC_I * 4u;

    CP_WAIT(0);
    __syncthreads();

    float acc0 = 0.0f, acc1 = 0.0f;
    if (y0 + 64 <= PP) {
#pragma unroll
        for (int i = 0; i < 16; ++i) {
            float r = radon_sample(cbase,
                                   fmaf((float)i, sa, wx0m),
                                   fmaf((float)i, ca, wy0m));
            if (i & 1) acc1 += r; else acc0 += r;
        }
    } else {
#pragma unroll
        for (int i = 0; i < 16; ++i) {
            float r = radon_sample(cbase,
                                   fmaf((float)i, sa, wx0m),
                                   fmaf((float)i, ca, wy0m));
            float g = (ybeg + i < PP) ? 1.0f : 0.0f;
            if (i & 1) acc1 = fmaf(g, r, acc1);
            else       acc0 = fmaf(g, r, acc0);
        }
    }
    float acc = acc0 + acc1;

    __syncthreads();
    red[ysub * 64 + xl] = acc;
    __syncthreads();
    if (tid < 64) {
        float s = ((red[tid] + red[64 + tid]) + red[128 + tid]) + red[192 + tid];
        int xo = x0 + tid;
        if (xo < PP)
            g_lpart[(size_t)blockIdx.y * TOT + a * PP + xo] = s;
    }
}

// --------------------------- reduce / normalize ----------------------------
__global__ void reduce_max_kernel() {
    __shared__ float smax[256];
    int idx = blockIdx.x * 256 + threadIdx.x;
    float v = -__int_as_float(0x7f800000);
    if (idx < TOT) {
        float s = 0.0f;
        for (int p = 0; p < NYT; p++) s += g_lpart[(size_t)p * TOT + idx];
        g_lines[idx] = s;
        v = s;
    }
    smax[threadIdx.x] = v;
    __syncthreads();
    for (int o = 128; o > 0; o >>= 1) {
        if (threadIdx.x < o)
            smax[threadIdx.x] = fmaxf(smax[threadIdx.x], smax[threadIdx.x + o]);
        __syncthreads();
    }
    if (threadIdx.x == 0) {
        unsigned u = __float_as_uint(smax[0]);
        unsigned enc = (u & 0x80000000u) ? ~u : (u | 0x80000000u);
        atomicMax(&g_maxbits, enc);
    }
}

__global__ void normalize_kernel(float* __restrict__ out) {
    int idx = blockIdx.x * 256 + threadIdx.x;
    if (idx >= TOT) return;
    unsigned u = g_maxbits;
    float mx = (u & 0x80000000u) ? __uint_as_float(u & 0x7fffffffu)
                                 : __uint_as_float(~u);
    int x = idx >> 5;
    int a = idx & 31;
    out[idx] = g_lines[a * PP + x] / mx;
}

// ---------------------------------------------------------------------------
extern "C" void kernel_launch(void* const* d_in, const int* in_sizes, int n_in,
                              void* d_out, int out_size) {
    const float* img = (const float*)d_in[0];
    float* out = (float*)d_out;

    static int s_init = 0;
    if (!s_init) {
        cudaFuncSetAttribute(gemm1_kernel,
                             cudaFuncAttributeMaxDynamicSharedMemorySize, SM_G1);
        cudaFuncSetAttribute(gemm2_kernel,
                             cudaFuncAttributeMaxDynamicSharedMemorySize, SM_G2);
        s_init = 1;
    }

    prep_kernel<<<NBB + NCG + NTS, 256>>>(img);

    __nv_bfloat16 *pCeh, *pCel, *pCoh, *pCol;
    cudaGetSymbolAddress((void**)&pCeh, g_Ceh);
    cudaGetSymbolAddress((void**)&pCel, g_Cel);
    cudaGetSymbolAddress((void**)&pCoh, g_Coh);
    cudaGetSymbolAddress((void**)&pCol, g_Col);

    // gemm1: mirror-pair tiles, emits As/Aa directly. grid 8n x 8m x 2par
    dim3 g1(HM / 128, HM / 128, 2);
    gemm1_kernel<<<g1, 256, SM_G1>>>(pCeh, pCel, pCoh, pCol);

    // gemm2: pad[m+PADB, PADB+2n'+p] = (p? Aa:As) . (p? Co:Ce)^T
    dim3 g2(HM / 128, MM / 128, 2);
    gemm2_kernel<<<g2, 256, SM_G2>>>(pCeh, pCel, pCoh, pCol);

    dim3 rg(NXT, NYT, NANG);
    radon_tiled_kernel<<<rg, 256>>>();

    reduce_max_kernel<<<(TOT + 255) / 256, 256>>>();
    normalize_kernel<<<(TOT + 255) / 256, 256>>>(out);
}

// round 14
// speedup vs baseline: 1.3744x; 1.0087x over previous
#include <cuda_runtime.h>
#include <cuda_bf16.h>
#include <cstdint>

// ---------------------------------------------------------------------------
// image_prj: D = dct2(image) [2048x2048, ortho] -> pad to 2198x2198 ->
// 32-angle radon (bilinear, WRAP) -> lines^T / max
// GEMMs: DCT even/odd fold (half FLOPs), gemm1 emits folded A directly.
// Radon: cp.async tile + bias-round bilinear; 6 blocks/SM (smem overlay +
// reg cap) for latency hiding.
// ---------------------------------------------------------------------------

#define MM    2048
#define HM    1024
#define PP    2198
#define PPS   2200
#define PADB  75
#define NANG  32
#define TOT   (NANG * PP)
#define NYT   35
#define NXT   35

__device__ __nv_bfloat16 g_Ceh[HM * HM], g_Cel[HM * HM];   // C even rows
__device__ __nv_bfloat16 g_Coh[HM * HM], g_Col[HM * HM];   // C odd rows
__device__ __nv_bfloat16 g_Bsh[MM * HM], g_Bsl[MM * HM];   // X^T fold-sum
__device__ __nv_bfloat16 g_Bah[MM * HM], g_Bal[MM * HM];   // X^T fold-diff
__device__ __nv_bfloat16 g_Ash[MM * HM], g_Asl[MM * HM];   // tmp fold-sum
__device__ __nv_bfloat16 g_Aah[MM * HM], g_Aal[MM * HM];   // tmp fold-diff
__device__ float    g_pad[PP * PPS];
__device__ float    g_lpart[NYT * TOT];
__device__ float    g_lines[TOT];
__device__ unsigned g_maxbits;

// ------------------------------ PTX helpers -------------------------------
__device__ __forceinline__ uint32_t smem_u32(const void* p) {
    uint32_t a;
    asm("{ .reg .u64 t; cvta.to.shared.u64 t, %1; cvt.u32.u64 %0, t; }"
        : "=r"(a) : "l"(p));
    return a;
}
#define CP_COMMIT() asm volatile("cp.async.commit_group;" ::: "memory")
#define CP_WAIT(n)  asm volatile("cp.async.wait_group %0;" :: "n"(n) : "memory")

__device__ __forceinline__ void cp16(uint32_t dst, const void* src) {
    asm volatile("cp.async.cg.shared.global [%0], [%1], 16;"
                 :: "r"(dst), "l"(src) : "memory");
}
__device__ __forceinline__ void cp4(uint32_t dst, const void* src) {
    asm volatile("cp.async.ca.shared.global [%0], [%1], 4;"
                 :: "r"(dst), "l"(src) : "memory");
}
__device__ __forceinline__ void ldsm4(uint32_t& r0, uint32_t& r1,
                                      uint32_t& r2, uint32_t& r3, uint32_t a) {
    asm volatile("ldmatrix.sync.aligned.m8n8.x4.shared.b16 {%0,%1,%2,%3}, [%4];"
                 : "=r"(r0), "=r"(r1), "=r"(r2), "=r"(r3) : "r"(a));
}
__device__ __forceinline__ void mma16816(float* d, const uint32_t* a,
                                         const uint32_t* b) {
    asm volatile("mma.sync.aligned.m16n8k16.row.col.f32.bf16.bf16.f32 "
                 "{%0,%1,%2,%3}, {%4,%5,%6,%7}, {%8,%9}, {%0,%1,%2,%3};"
                 : "+f"(d[0]), "+f"(d[1]), "+f"(d[2]), "+f"(d[3])
                 : "r"(a[0]), "r"(a[1]), "r"(a[2]), "r"(a[3]),
                   "r"(b[0]), "r"(b[1]));
}
__device__ __forceinline__ uint32_t sw128(uint32_t b) { return b ^ ((b >> 3) & 0x70); }
__device__ __forceinline__ void bf16split(float v, __nv_bfloat16& h, __nv_bfloat16& l) {
    h = __float2bfloat16(v);
    l = __float2bfloat16(v - __bfloat162float(h));
}

// --------------------------- merged prep kernel ----------------------------
#define NB1 (150 * PP)
#define NB2 (MM * 150)
#define NBB ((NB1 + NB2 + 255) / 256)
#define NCG (2 * HM * HM / 256)
#define NTS ((HM / 32) * (MM / 32))

__global__ void prep_kernel(const float* __restrict__ img) {
    __shared__ float ts[32][33];
    __shared__ float ta[32][33];
    int b = blockIdx.x;
    int tid = threadIdx.x;

    if (b < NBB) {
        int idx = b * 256 + tid;
        if (idx == 0) g_maxbits = 0u;
        if (idx < NB1) {
            int r = idx / PP, c = idx % PP;
            int row = (r < 75) ? r : (2123 + r - 75);
            g_pad[(size_t)row * PPS + c] = 0.0f;
        } else if (idx < NB1 + NB2) {
            int j = idx - NB1;
            int r = j / 150, c = j % 150;
            int col = (c < 75) ? c : (2123 + c - 75);
            g_pad[(size_t)(75 + r) * PPS + col] = 0.0f;
        }
        return;
    }
    b -= NBB;
    if (b < NCG) {
        int idx = b * 256 + tid;
        int par = idx >> 20;
        int mp  = (idx >> 10) & (HM - 1);
        int n   = idx & (HM - 1);
        int k   = 2 * mp + par;
        int r   = ((2 * n + 1) * k) & (4 * MM - 1);
        float t = (float)r * (1.0f / (2.0f * MM));
        float c = cospif(t);
        float s = (k == 0) ? 0.022097086912079608f : 0.03125f;
        float v = s * c;
        __nv_bfloat16 h, l; bf16split(v, h, l);
        size_t o = (size_t)mp * HM + n;
        if (par) { g_Coh[o] = h; g_Col[o] = l; }
        else     { g_Ceh[o] = h; g_Cel[o] = l; }
        return;
    }
    b -= NCG;
    {
        int kt = b & 31, nt = b >> 5;
        int kb = kt * 32, nb = nt * 32;
        int tx = tid & 31, ty = tid >> 5;
#pragma unroll
        for (int i = 0; i < 4; i++) {
            int k = kb + ty + i * 8;
            float v1 = img[(size_t)k * MM + nb + tx];
            float v2 = img[(size_t)(MM - 1 - k) * MM + nb + tx];
            ts[ty + i * 8][tx] = v1 + v2;
            ta[ty + i * 8][tx] = v1 - v2;
        }
        __syncthreads();
#pragma unroll
        for (int i = 0; i < 4; i++) {
            int nl = ty + i * 8;
            size_t o = (size_t)(nb + nl) * HM + kb + tx;
            __nv_bfloat16 h, l;
            bf16split(ts[tx][nl], h, l); g_Bsh[o] = h; g_Bsl[o] = l;
            bf16split(ta[tx][nl], h, l); g_Bah[o] = h; g_Bal[o] = l;
        }
    }
}

// --------------------- gemm1: mirror-pair, fold-emitting --------------------
#define KC      64
#define NCH2    (HM / KC)          // 16
#define T_T     16384
#define ST1_SZ  (6 * T_T)          // 96KB
#define SM_G1   (2 * ST1_SZ)       // 192KB

__device__ __forceinline__ void g1_load_chunk(
    uint32_t st,
    const __nv_bfloat16* __restrict__ Ah, const __nv_bfloat16* __restrict__ Al,
    const __nv_bfloat16* __restrict__ Bh, const __nv_bfloat16* __restrict__ Bl,
    int m0, int n0, int k0, int tid)
{
#pragma unroll
    for (int t = 0; t < 24; ++t) {
        int idx  = tid + t * 256;
        int tile = idx >> 10;
        int r    = (idx >> 3) & 127;
        int seg  = idx & 7;
        const __nv_bfloat16* src;
        int row;
        switch (tile) {
            case 0: src = Ah; row = m0 + r; break;
            case 1: src = Al; row = m0 + r; break;
            case 2: src = Bh; row = n0 + r; break;
            case 3: src = Bl; row = n0 + r; break;
            case 4: src = Bh; row = MM - 1 - n0 - r; break;
            default: src = Bl; row = MM - 1 - n0 - r; break;
        }
        cp16(st + tile * T_T + sw128(r * 128 + seg * 16),
             src + (size_t)row * HM + k0 + seg * 8);
    }
}

__global__ __launch_bounds__(256, 1) void gemm1_kernel(
    const __nv_bfloat16* __restrict__ Ah0, const __nv_bfloat16* __restrict__ Al0,
    const __nv_bfloat16* __restrict__ Ah1, const __nv_bfloat16* __restrict__ Al1)
{
    extern __shared__ char smem[];
    uint32_t sb = smem_u32(smem);
    int tid = threadIdx.x, wid = tid >> 5, lane = tid & 31;
    int m0 = blockIdx.y * 128, n0 = blockIdx.x * 128;
    int par = blockIdx.z;
    int wm = wid & 1, wn = wid >> 1;

    const __nv_bfloat16* Ah = par ? Ah1 : Ah0;
    const __nv_bfloat16* Al = par ? Al1 : Al0;
    const __nv_bfloat16* Bh = par ? g_Bah : g_Bsh;
    const __nv_bfloat16* Bl = par ? g_Bal : g_Bsl;

    float acc0[4][4][4], acc1[4][4][4];
#pragma unroll
    for (int i = 0; i < 4; i++)
#pragma unroll
        for (int j = 0; j < 4; j++)
#pragma unroll
            for (int q = 0; q < 4; q++) { acc0[i][j][q] = 0.0f; acc1[i][j][q] = 0.0f; }

    int aRow  = wm * 64 + (lane & 7) + ((lane >> 3) & 1) * 8;
    int aSegB = lane >> 4;
    uint32_t aXor  = (uint32_t)(aRow & 7) << 4;
    uint32_t aBase = (uint32_t)aRow * 128;
    int bRow  = wn * 32 + (lane & 7) + ((lane >> 4) & 1) * 8;
    int bSegB = (lane >> 3) & 1;
    uint32_t bXor  = (uint32_t)(bRow & 7) << 4;
    uint32_t bBase = (uint32_t)bRow * 128;

    g1_load_chunk(sb + 0 * ST1_SZ, Ah, Al, Bh, Bl, m0, n0, 0 * KC, tid); CP_COMMIT();
    g1_load_chunk(sb + 1 * ST1_SZ, Ah, Al, Bh, Bl, m0, n0, 1 * KC, tid); CP_COMMIT();

    for (int c = 0; c < NCH2; ++c) {
        if (c + 1 < NCH2) CP_WAIT(1);
        else              CP_WAIT(0);
        __syncthreads();

        uint32_t st = sb + (c & 1) * ST1_SZ;
        uint32_t sAh = st, sAl = st + T_T;
        uint32_t sB0h = st + 2 * T_T, sB0l = st + 3 * T_T;
        uint32_t sB1h = st + 4 * T_T, sB1l = st + 5 * T_T;

#pragma unroll
        for (int ks = 0; ks < 4; ++ks) {
            uint32_t aSegOff = (uint32_t)(((ks * 2 + aSegB) * 16) ^ aXor);
            uint32_t bSegOff = (uint32_t)(((ks * 2 + bSegB) * 16) ^ bXor);
            uint32_t b0h[2][4], b0l[2][4], b1h[2][4], b1l[2][4];
#pragma unroll
            for (int p = 0; p < 2; ++p) {
                uint32_t off = bBase + p * 2048 + bSegOff;
                ldsm4(b0h[p][0], b0h[p][1], b0h[p][2], b0h[p][3], sB0h + off);
                ldsm4(b0l[p][0], b0l[p][1], b0l[p][2], b0l[p][3], sB0l + off);
                ldsm4(b1h[p][0], b1h[p][1], b1h[p][2], b1h[p][3], sB1h + off);
                ldsm4(b1l[p][0], b1l[p][1], b1l[p][2], b1l[p][3], sB1l + off);
            }
#pragma unroll
            for (int mt = 0; mt < 4; ++mt) {
                uint32_t ah[4], al[4];
                uint32_t off = aBase + mt * 2048 + aSegOff;
                ldsm4(ah[0], ah[1], ah[2], ah[3], sAh + off);
                ldsm4(al[0], al[1], al[2], al[3], sAl + off);
#pragma unroll
                for (int nt = 0; nt < 4; ++nt) {
                    const uint32_t* p0h = &b0h[nt >> 1][(nt & 1) * 2];
                    const uint32_t* p0l = &b0l[nt >> 1][(nt & 1) * 2];
                    const uint32_t* p1h = &b1h[nt >> 1][(nt & 1) * 2];
                    const uint32_t* p1l = &b1l[nt >> 1][(nt & 1) * 2];
                    mma16816(acc0[mt][nt], ah, p0h);
                    mma16816(acc0[mt][nt], ah, p0l);
                    mma16816(acc0[mt][nt], al, p0h);
                    mma16816(acc1[mt][nt], ah, p1h);
                    mma16816(acc1[mt][nt], ah, p1l);
                    mma16816(acc1[mt][nt], al, p1h);
                }
            }
        }
        __syncthreads();
        if (c + 2 < NCH2) {
            g1_load_chunk(sb + (c & 1) * ST1_SZ, Ah, Al, Bh, Bl,
                          m0, n0, (c + 2) * KC, tid);
        }
        CP_COMMIT();
    }

#pragma unroll
    for (int mt = 0; mt < 4; ++mt)
#pragma unroll
        for (int nt = 0; nt < 4; ++nt) {
#pragma unroll
            for (int h = 0; h < 2; ++h) {
                int row = m0 + wm * 64 + mt * 16 + (lane >> 2) + h * 8;
                int col = n0 + wn * 32 + nt * 8 + (lane & 3) * 2;
                float v0 = acc0[mt][nt][h * 2 + 0];
                float v1 = acc0[mt][nt][h * 2 + 1];
                float u0 = acc1[mt][nt][h * 2 + 0];
                float u1 = acc1[mt][nt][h * 2 + 1];
                size_t o = (size_t)(2 * row + par) * HM + col;
                __nv_bfloat16 h0, l0, h1, l1;
                bf16split(v0 + u0, h0, l0); bf16split(v1 + u1, h1, l1);
                __nv_bfloat162 hp, lp;
                hp.x = h0; hp.y = h1; lp.x = l0; lp.y = l1;
                *(__nv_bfloat162*)&g_Ash[o] = hp;
                *(__nv_bfloat162*)&g_Asl[o] = lp;
                bf16split(v0 - u0, h0, l0); bf16split(v1 - u1, h1, l1);
                hp.x = h0; hp.y = h1; lp.x = l0; lp.y = l1;
                *(__nv_bfloat162*)&g_Aah[o] = hp;
                *(__nv_bfloat162*)&g_Aal[o] = lp;
            }
        }
}

// ------------------------- gemm2 (K=1024) ----------------------------------
#define ST_SZ   (4 * T_T)
#define STAGES  3
#define SM_G2   (STAGES * ST_SZ)

__device__ __forceinline__ void g2_load_chunk(
    uint32_t st,
    const __nv_bfloat16* __restrict__ Ah, const __nv_bfloat16* __restrict__ Al,
    const __nv_bfloat16* __restrict__ Bh, const __nv_bfloat16* __restrict__ Bl,
    int m0, int n0, int k0, int tid)
{
#pragma unroll
    for (int t = 0; t < 16; ++t) {
        int idx  = tid + t * 256;
        int tile = idx >> 10;
        int r    = (idx >> 3) & 127;
        int seg  = idx & 7;
        const __nv_bfloat16* src;
        int rb;
        if      (tile == 0) { src = Ah; rb = m0; }
        else if (tile == 1) { src = Al; rb = m0; }
        else if (tile == 2) { src = Bh; rb = n0; }
        else                { src = Bl; rb = n0; }
        cp16(st + tile * T_T + sw128(r * 128 + seg * 16),
             src + (size_t)(rb + r) * HM + k0 + seg * 8);
    }
}

__global__ __launch_bounds__(256, 1) void gemm2_kernel(
    const __nv_bfloat16* __restrict__ Bh0, const __nv_bfloat16* __restrict__ Bl0,
    const __nv_bfloat16* __restrict__ Bh1, const __nv_bfloat16* __restrict__ Bl1)
{
    extern __shared__ char smem[];
    uint32_t sb = smem_u32(smem);
    int tid = threadIdx.x, wid = tid >> 5, lane = tid & 31;
    int m0 = blockIdx.y * 128, n0 = blockIdx.x * 128;
    int par = blockIdx.z;
    int wm = wid & 1, wn = wid >> 1;

    const __nv_bfloat16* Ah = par ? g_Aah : g_Ash;
    const __nv_bfloat16* Al = par ? g_Aal : g_Asl;
    const __nv_bfloat16* Bh = par ? Bh1 : Bh0;
    const __nv_bfloat16* Bl = par ? Bl1 : Bl0;

    float acc[4][4][4];
#pragma unroll
    for (int i = 0; i < 4; i++)
#pragma unroll
        for (int j = 0; j < 4; j++)
#pragma unroll
            for (int q = 0; q < 4; q++) acc[i][j][q] = 0.0f;

    int aRow  = wm * 64 + (lane & 7) + ((lane >> 3) & 1) * 8;
    int aSegB = lane >> 4;
    uint32_t aXor  = (uint32_t)(aRow & 7) << 4;
    uint32_t aBase = (uint32_t)aRow * 128;
    int bRow  = wn * 32 + (lane & 7) + ((lane >> 4) & 1) * 8;
    int bSegB = (lane >> 3) & 1;
    uint32_t bXor  = (uint32_t)(bRow & 7) << 4;
    uint32_t bBase = (uint32_t)bRow * 128;

    g2_load_chunk(sb + 0 * ST_SZ, Ah, Al, Bh, Bl, m0, n0, 0 * KC, tid); CP_COMMIT();
    g2_load_chunk(sb + 1 * ST_SZ, Ah, Al, Bh, Bl, m0, n0, 1 * KC, tid); CP_COMMIT();
    g2_load_chunk(sb + 2 * ST_SZ, Ah, Al, Bh, Bl, m0, n0, 2 * KC, tid); CP_COMMIT();

    for (int c = 0; c < NCH2; ++c) {
        if      (c <= NCH2 - 3) CP_WAIT(2);
        else if (c == NCH2 - 2) CP_WAIT(1);
        else                    CP_WAIT(0);
        __syncthreads();

        uint32_t st = sb + (c % STAGES) * ST_SZ;
        uint32_t sAh = st, sAl = st + T_T, sBh = st + 2 * T_T, sBl = st + 3 * T_T;

#pragma unroll
        for (int ks = 0; ks < 4; ++ks) {
            uint32_t ah[4][4], al[4][4], bh[2][4], bl[2][4];
            uint32_t aSegOff = (uint32_t)(((ks * 2 + aSegB) * 16) ^ aXor);
            uint32_t bSegOff = (uint32_t)(((ks * 2 + bSegB) * 16) ^ bXor);
#pragma unroll
            for (int mt = 0; mt < 4; ++mt) {
                uint32_t off = aBase + mt * 2048 + aSegOff;
                ldsm4(ah[mt][0], ah[mt][1], ah[mt][2], ah[mt][3], sAh + off);
                ldsm4(al[mt][0], al[mt][1], al[mt][2], al[mt][3], sAl + off);
            }
#pragma unroll
            for (int p = 0; p < 2; ++p) {
                uint32_t off = bBase + p * 2048 + bSegOff;
                ldsm4(bh[p][0], bh[p][1], bh[p][2], bh[p][3], sBh + off);
                ldsm4(bl[p][0], bl[p][1], bl[p][2], bl[p][3], sBl + off);
            }
#pragma unroll
            for (int mt = 0; mt < 4; ++mt)
#pragma unroll
                for (int nt = 0; nt < 4; ++nt) {
                    const uint32_t* pbh = &bh[nt >> 1][(nt & 1) * 2];
                    const uint32_t* pbl = &bl[nt >> 1][(nt & 1) * 2];
                    mma16816(acc[mt][nt], ah[mt], pbh);
                    mma16816(acc[mt][nt], ah[mt], pbl);
                    mma16816(acc[mt][nt], al[mt], pbh);
                }
        }
        __syncthreads();
        if (c + STAGES < NCH2) {
            g2_load_chunk(sb + (c % STAGES) * ST_SZ, Ah, Al, Bh, Bl,
                          m0, n0, (c + STAGES) * KC, tid);
        }
        CP_COMMIT();
    }

#pragma unroll
    for (int mt = 0; mt < 4; ++mt)
#pragma unroll
        for (int nt = 0; nt < 4; ++nt) {
#pragma unroll
            for (int h = 0; h < 2; ++h) {
                int row = m0 + wm * 64 + mt * 16 + (lane >> 2) + h * 8;
                int col = n0 + wn * 32 + nt * 8 + (lane & 3) * 2;
                float v0 = acc[mt][nt][h * 2 + 0];
                float v1 = acc[mt][nt][h * 2 + 1];
                size_t o = (size_t)(row + PADB) * PPS + PADB + 2 * col + par;
                g_pad[o]     = v0;
                g_pad[o + 2] = v1;
            }
        }
}

// ------------------------------ tiled radon --------------------------------
#define RSW 100
#define RSH 95
#define RMAGIC 12582912.0f       // 1.5 * 2^23
#define RMAGIC_I 0x4B400000

__device__ __forceinline__ float radon_sample(
    const float* __restrict__ smbase, uint32_t cbase, float txm, float tym)
{
    float ux = txm + RMAGIC;
    float uy = tym + RMAGIC;
    float wx = (txm - (ux - RMAGIC)) + 0.5f;
    float wy = (tym - (uy - RMAGIC)) + 0.5f;
    uint32_t addr = cbase + __float_as_uint(uy) * (RSW * 4u)
                          + __float_as_uint(ux) * 4u;
    float s00, s01, s10, s11;
    asm volatile("ld.shared.f32 %0, [%1];"       : "=f"(s00) : "r"(addr));
    asm volatile("ld.shared.f32 %0, [%1+4];"     : "=f"(s01) : "r"(addr));
    asm volatile("ld.shared.f32 %0, [%1+400];"   : "=f"(s10) : "r"(addr));
    asm volatile("ld.shared.f32 %0, [%1+404];"   : "=f"(s11) : "r"(addr));
    float top = fmaf(wx, s01 - s00, s00);
    float bot = fmaf(wx, s11 - s10, s10);
    return fmaf(wy, bot - top, top);
}

__global__ __launch_bounds__(256, 6) void radon_tiled_kernel() {
    __shared__ float sm[RSH * RSW];   // reduction overlays sm[0..255] at end

    int a  = blockIdx.z;
    int x0 = blockIdx.x * 64;
    int y0 = blockIdx.y * 64;
    int tid = threadIdx.x, wid = tid >> 5, lane = tid & 31;

    float ang = (float)(3.141592653589793 * (double)a / 31.0);
    float ca = cosf(ang);
    float sa = sinf(ang);
    const float cen = (float)(PP / 2);
    float c1 = cen * (ca + sa - 1.0f);
    float c2 = cen * (ca - sa - 1.0f);

    float xf0 = (float)x0, xf1 = (float)(x0 + 63);
    float yf0 = (float)y0, yf1 = (float)(y0 + 63);
    float u00 = ca * xf0 + sa * yf0 - c1, u01 = ca * xf0 + sa * yf1 - c1;
    float u10 = ca * xf1 + sa * yf0 - c1, u11 = ca * xf1 + sa * yf1 - c1;
    float v00 = -sa * xf0 + ca * yf0 - c2, v01 = -sa * xf0 + ca * yf1 - c2;
    float v10 = -sa * xf1 + ca * yf0 - c2, v11 = -sa * xf1 + ca * yf1 - c2;
    float umin = fminf(fminf(u00, u01), fminf(u10, u11));
    float umax = fmaxf(fmaxf(u00, u01), fmaxf(u10, u11));
    float vmin = fminf(fminf(v00, v01), fminf(v10, v11));
    float vmax = fmaxf(fmaxf(v00, v01), fmaxf(v10, v11));

    int u0i = (int)floorf(umin) - 1;
    int v0i = (int)floorf(vmin) - 1;
    int W = (int)floorf(umax) + 2 - u0i + 1;
    int H = (int)floorf(vmax) + 2 - v0i + 1;

    int u0m = u0i % PP; if (u0m < 0) u0m += PP;
    int v0m = v0i % PP; if (v0m < 0) v0m += PP;

    int sft  = u0m & 3;
    int u0s  = u0i - sft;
    int u0ms = u0m - sft;
    int W4   = (W + sft + 3) & ~3;

    uint32_t smb = smem_u32(sm);
    if (u0ms + W4 <= PP) {
        int nq = W4 >> 2;
        for (int r = wid; r < H; r += 8) {
            int rm = v0m + r; if (rm >= PP) rm -= PP;
            const float* src = g_pad + (size_t)rm * PPS + u0ms;
            uint32_t drow = smb + (uint32_t)(r * RSW) * 4;
            for (int q = lane; q < nq; q += 32)
                cp16(drow + (uint32_t)q * 16, src + q * 4);
        }
    } else {
        for (int r = wid; r < H; r += 8) {
            int rm = v0m + r; if (rm >= PP) rm -= PP;
            const float* rowp = g_pad + (size_t)rm * PPS;
            uint32_t drow = smb + (uint32_t)(r * RSW) * 4;
            for (int c = lane; c < W4; c += 32) {
                int cm = u0ms + c; if (cm >= PP) cm -= PP;
                cp4(drow + (uint32_t)c * 4, rowp + cm);
            }
        }
    }
    CP_COMMIT();

    int xl   = tid & 63;
    int ysub = tid >> 6;
    int x    = x0 + xl;
    float xf = (float)x;
    float bx = ca * xf - c1;
    float by = -sa * xf - c2;

    int ybeg = y0 + ysub * 16;
    float ybf  = (float)ybeg;
    float xin0 = fmaf(sa, ybf, bx);
    float yin0 = fmaf(ca, ybf, by);
    float fx0 = floorf(xin0);
    float fy0 = floorf(yin0);
    float wx0m = (xin0 - fx0) - 0.5f;
    float wy0m = (yin0 - fy0) - 0.5f;
    int   base0 = ((int)fy0 - v0i) * RSW + ((int)fx0 - u0s);
    uint32_t cbase = smb + (uint32_t)base0 * 4u
                   - (uint32_t)RMAGIC_I * (RSW * 4u)
                   - (uint32_t)RMAGIC_I * 4u;

    CP_WAIT(0);
    __syncthreads();

    float acc0 = 0.0f, acc1 = 0.0f;
    if (y0 + 64 <= PP) {
#pragma unroll
        for (int i = 0; i < 16; ++i) {
            float r = radon_sample(sm, cbase,
                                   fmaf((float)i, sa, wx0m),
                                   fmaf((float)i, ca, wy0m));
            if (i & 1) acc1 += r; else acc0 += r;
        }
    } else {
#pragma unroll
        for (int i = 0; i < 16; ++i) {
            float r = radon_sample(sm, cbase,
                                   fmaf((float)i, sa, wx0m),
                                   fmaf((float)i, ca, wy0m));
            float g = (ybeg + i < PP) ? 1.0f : 0.0f;
            if (i & 1) acc1 = fmaf(g, r, acc1);
            else       acc0 = fmaf(g, r, acc0);
        }
    }
    float acc = acc0 + acc1;

    // reduction overlays the (now dead) footprint tile
    __syncthreads();
    sm[ysub * 64 + xl] = acc;
    __syncthreads();
    if (tid < 64) {
        float s = ((sm[tid] + sm[64 + tid]) + sm[128 + tid]) + sm[192 + tid];
        int xo = x0 + tid;
        if (xo < PP)
            g_lpart[(size_t)blockIdx.y * TOT + a * PP + xo] = s;
    }
}

// --------------------------- reduce / normalize ----------------------------
__global__ void reduce_max_kernel() {
    __shared__ float smax[256];
    int idx = blockIdx.x * 256 + threadIdx.x;
    float v = -__int_as_float(0x7f800000);
    if (idx < TOT) {
        float s = 0.0f;
        for (int p = 0; p < NYT; p++) s += g_lpart[(size_t)p * TOT + idx];
        g_lines[idx] = s;
        v = s;
    }
    smax[threadIdx.x] = v;
    __syncthreads();
    for (int o = 128; o > 0; o >>= 1) {
        if (threadIdx.x < o)
            smax[threadIdx.x] = fmaxf(smax[threadIdx.x], smax[threadIdx.x + o]);
        __syncthreads();
    }
    if (threadIdx.x == 0) {
        unsigned u = __float_as_uint(smax[0]);
        unsigned enc = (u & 0x80000000u) ? ~u : (u | 0x80000000u);
        atomicMax(&g_maxbits, enc);
    }
}

__global__ void normalize_kernel(float* __restrict__ out) {
    int idx = blockIdx.x * 256 + threadIdx.x;
    if (idx >= TOT) return;
    unsigned u = g_maxbits;
    float mx = (u & 0x80000000u) ? __uint_as_float(u & 0x7fffffffu)
                                 : __uint_as_float(~u);
    int x = idx >> 5;
    int a = idx & 31;
    out[idx] = g_lines[a * PP + x] / mx;
}

// ---------------------------------------------------------------------------
extern "C" void kernel_launch(void* const* d_in, const int* in_sizes, int n_in,
                              void* d_out, int out_size) {
    const float* img = (const float*)d_in[0];
    float* out = (float*)d_out;

    static int s_init = 0;
    if (!s_init) {
        cudaFuncSetAttribute(gemm1_kernel,
                             cudaFuncAttributeMaxDynamicSharedMemorySize, SM_G1);
        cudaFuncSetAttribute(gemm2_kernel,
                             cudaFuncAttributeMaxDynamicSharedMemorySize, SM_G2);
        cudaFuncSetAttribute(radon_tiled_kernel,
                             cudaFuncAttributePreferredSharedMemoryCarveout, 100);
        s_init = 1;
    }

    prep_kernel<<<NBB + NCG + NTS, 256>>>(img);

    __nv_bfloat16 *pCeh, *pCel, *pCoh, *pCol;
    cudaGetSymbolAddress((void**)&pCeh, g_Ceh);
    cudaGetSymbolAddress((void**)&pCel, g_Cel);
    cudaGetSymbolAddress((void**)&pCoh, g_Coh);
    cudaGetSymbolAddress((void**)&pCol, g_Col);

    dim3 g1(HM / 128, HM / 128, 2);
    gemm1_kernel<<<g1, 256, SM_G1>>>(pCeh, pCel, pCoh, pCol);

    dim3 g2(HM / 128, MM / 128, 2);
    gemm2_kernel<<<g2, 256, SM_G2>>>(pCeh, pCel, pCoh, pCol);

    dim3 rg(NXT, NYT, NANG);
    radon_tiled_kernel<<<rg, 256>>>();

    reduce_max_kernel<<<(TOT + 255) / 256, 256>>>();
    normalize_kernel<<<(TOT + 255) / 256, 256>>>(out);
}

// round 16
// speedup vs baseline: 1.3998x; 1.0185x over previous
#include <cuda_runtime.h>
#include <cuda_bf16.h>
#include <cstdint>

// ---------------------------------------------------------------------------
// image_prj: D = dct2(image) [2048x2048, ortho] -> pad to 2198x2198 ->
// 32-angle radon (bilinear, WRAP) -> lines^T / max
// GEMMs: DCT even/odd fold (half FLOPs), gemm1 emits folded A directly.
// Radon: cp.async tile (93x100, 16B-aligned rows, 6 blocks/SM) +
// bias-round bilinear.
// ---------------------------------------------------------------------------

#define MM    2048
#define HM    1024
#define PP    2198
#define PPS   2200
#define PADB  75
#define NANG  32
#define TOT   (NANG * PP)
#define NYT   35
#define NXT   35

__device__ __nv_bfloat16 g_Ceh[HM * HM], g_Cel[HM * HM];   // C even rows
__device__ __nv_bfloat16 g_Coh[HM * HM], g_Col[HM * HM];   // C odd rows
__device__ __nv_bfloat16 g_Bsh[MM * HM], g_Bsl[MM * HM];   // X^T fold-sum
__device__ __nv_bfloat16 g_Bah[MM * HM], g_Bal[MM * HM];   // X^T fold-diff
__device__ __nv_bfloat16 g_Ash[MM * HM], g_Asl[MM * HM];   // tmp fold-sum
__device__ __nv_bfloat16 g_Aah[MM * HM], g_Aal[MM * HM];   // tmp fold-diff
__device__ float    g_pad[PP * PPS];
__device__ float    g_lpart[NYT * TOT];
__device__ float    g_lines[TOT];
__device__ unsigned g_maxbits;

// ------------------------------ PTX helpers -------------------------------
__device__ __forceinline__ uint32_t smem_u32(const void* p) {
    uint32_t a;
    asm("{ .reg .u64 t; cvta.to.shared.u64 t, %1; cvt.u32.u64 %0, t; }"
        : "=r"(a) : "l"(p));
    return a;
}
#define CP_COMMIT() asm volatile("cp.async.commit_group;" ::: "memory")
#define CP_WAIT(n)  asm volatile("cp.async.wait_group %0;" :: "n"(n) : "memory")

__device__ __forceinline__ void cp16(uint32_t dst, const void* src) {
    asm volatile("cp.async.cg.shared.global [%0], [%1], 16;"
                 :: "r"(dst), "l"(src) : "memory");
}
__device__ __forceinline__ void cp4(uint32_t dst, const void* src) {
    asm volatile("cp.async.ca.shared.global [%0], [%1], 4;"
                 :: "r"(dst), "l"(src) : "memory");
}
__device__ __forceinline__ void ldsm4(uint32_t& r0, uint32_t& r1,
                                      uint32_t& r2, uint32_t& r3, uint32_t a) {
    asm volatile("ldmatrix.sync.aligned.m8n8.x4.shared.b16 {%0,%1,%2,%3}, [%4];"
                 : "=r"(r0), "=r"(r1), "=r"(r2), "=r"(r3) : "r"(a));
}
__device__ __forceinline__ void mma16816(float* d, const uint32_t* a,
                                         const uint32_t* b) {
    asm volatile("mma.sync.aligned.m16n8k16.row.col.f32.bf16.bf16.f32 "
                 "{%0,%1,%2,%3}, {%4,%5,%6,%7}, {%8,%9}, {%0,%1,%2,%3};"
                 : "+f"(d[0]), "+f"(d[1]), "+f"(d[2]), "+f"(d[3])
                 : "r"(a[0]), "r"(a[1]), "r"(a[2]), "r"(a[3]),
                   "r"(b[0]), "r"(b[1]));
}
__device__ __forceinline__ uint32_t sw128(uint32_t b) { return b ^ ((b >> 3) & 0x70); }
__device__ __forceinline__ void bf16split(float v, __nv_bfloat16& h, __nv_bfloat16& l) {
    h = __float2bfloat16(v);
    l = __float2bfloat16(v - __bfloat162float(h));
}

// --------------------------- merged prep kernel ----------------------------
#define NB1 (150 * PP)
#define NB2 (MM * 150)
#define NBB ((NB1 + NB2 + 255) / 256)
#define NCG (2 * HM * HM / 256)
#define NTS ((HM / 32) * (MM / 32))

__global__ void prep_kernel(const float* __restrict__ img) {
    __shared__ float ts[32][33];
    __shared__ float ta[32][33];
    int b = blockIdx.x;
    int tid = threadIdx.x;

    if (b < NBB) {
        int idx = b * 256 + tid;
        if (idx == 0) g_maxbits = 0u;
        if (idx < NB1) {
            int r = idx / PP, c = idx % PP;
            int row = (r < 75) ? r : (2123 + r - 75);
            g_pad[(size_t)row * PPS + c] = 0.0f;
        } else if (idx < NB1 + NB2) {
            int j = idx - NB1;
            int r = j / 150, c = j % 150;
            int col = (c < 75) ? c : (2123 + c - 75);
            g_pad[(size_t)(75 + r) * PPS + col] = 0.0f;
        }
        return;
    }
    b -= NBB;
    if (b < NCG) {
        int idx = b * 256 + tid;
        int par = idx >> 20;
        int mp  = (idx >> 10) & (HM - 1);
        int n   = idx & (HM - 1);
        int k   = 2 * mp + par;
        int r   = ((2 * n + 1) * k) & (4 * MM - 1);
        float t = (float)r * (1.0f / (2.0f * MM));
        float c = cospif(t);
        float s = (k == 0) ? 0.022097086912079608f : 0.03125f;
        float v = s * c;
        __nv_bfloat16 h, l; bf16split(v, h, l);
        size_t o = (size_t)mp * HM + n;
        if (par) { g_Coh[o] = h; g_Col[o] = l; }
        else     { g_Ceh[o] = h; g_Cel[o] = l; }
        return;
    }
    b -= NCG;
    {
        int kt = b & 31, nt = b >> 5;
        int kb = kt * 32, nb = nt * 32;
        int tx = tid & 31, ty = tid >> 5;
#pragma unroll
        for (int i = 0; i < 4; i++) {
            int k = kb + ty + i * 8;
            float v1 = img[(size_t)k * MM + nb + tx];
            float v2 = img[(size_t)(MM - 1 - k) * MM + nb + tx];
            ts[ty + i * 8][tx] = v1 + v2;
            ta[ty + i * 8][tx] = v1 - v2;
        }
        __syncthreads();
#pragma unroll
        for (int i = 0; i < 4; i++) {
            int nl = ty + i * 8;
            size_t o = (size_t)(nb + nl) * HM + kb + tx;
            __nv_bfloat16 h, l;
            bf16split(ts[tx][nl], h, l); g_Bsh[o] = h; g_Bsl[o] = l;
            bf16split(ta[tx][nl], h, l); g_Bah[o] = h; g_Bal[o] = l;
        }
    }
}

// --------------------- gemm1: mirror-pair, fold-emitting --------------------
#define KC      64
#define NCH2    (HM / KC)          // 16
#define T_T     16384
#define ST1_SZ  (6 * T_T)          // 96KB
#define SM_G1   (2 * ST1_SZ)       // 192KB

__device__ __forceinline__ void g1_load_chunk(
    uint32_t st,
    const __nv_bfloat16* __restrict__ Ah, const __nv_bfloat16* __restrict__ Al,
    const __nv_bfloat16* __restrict__ Bh, const __nv_bfloat16* __restrict__ Bl,
    int m0, int n0, int k0, int tid)
{
#pragma unroll
    for (int t = 0; t < 24; ++t) {
        int idx  = tid + t * 256;
        int tile = idx >> 10;
        int r    = (idx >> 3) & 127;
        int seg  = idx & 7;
        const __nv_bfloat16* src;
        int row;
        switch (tile) {
            case 0: src = Ah; row = m0 + r; break;
            case 1: src = Al; row = m0 + r; break;
            case 2: src = Bh; row = n0 + r; break;
            case 3: src = Bl; row = n0 + r; break;
            case 4: src = Bh; row = MM - 1 - n0 - r; break;
            default: src = Bl; row = MM - 1 - n0 - r; break;
        }
        cp16(st + tile * T_T + sw128(r * 128 + seg * 16),
             src + (size_t)row * HM + k0 + seg * 8);
    }
}

__global__ __launch_bounds__(256, 1) void gemm1_kernel(
    const __nv_bfloat16* __restrict__ Ah0, const __nv_bfloat16* __restrict__ Al0,
    const __nv_bfloat16* __restrict__ Ah1, const __nv_bfloat16* __restrict__ Al1)
{
    extern __shared__ char smem[];
    uint32_t sb = smem_u32(smem);
    int tid = threadIdx.x, wid = tid >> 5, lane = tid & 31;
    int m0 = blockIdx.y * 128, n0 = blockIdx.x * 128;
    int par = blockIdx.z;
    int wm = wid & 1, wn = wid >> 1;

    const __nv_bfloat16* Ah = par ? Ah1 : Ah0;
    const __nv_bfloat16* Al = par ? Al1 : Al0;
    const __nv_bfloat16* Bh = par ? g_Bah : g_Bsh;
    const __nv_bfloat16* Bl = par ? g_Bal : g_Bsl;

    float acc0[4][4][4], acc1[4][4][4];
#pragma unroll
    for (int i = 0; i < 4; i++)
#pragma unroll
        for (int j = 0; j < 4; j++)
#pragma unroll
            for (int q = 0; q < 4; q++) { acc0[i][j][q] = 0.0f; acc1[i][j][q] = 0.0f; }

    int aRow  = wm * 64 + (lane & 7) + ((lane >> 3) & 1) * 8;
    int aSegB = lane >> 4;
    uint32_t aXor  = (uint32_t)(aRow & 7) << 4;
    uint32_t aBase = (uint32_t)aRow * 128;
    int bRow  = wn * 32 + (lane & 7) + ((lane >> 4) & 1) * 8;
    int bSegB = (lane >> 3) & 1;
    uint32_t bXor  = (uint32_t)(bRow & 7) << 4;
    uint32_t bBase = (uint32_t)bRow * 128;

    g1_load_chunk(sb + 0 * ST1_SZ, Ah, Al, Bh, Bl, m0, n0, 0 * KC, tid); CP_COMMIT();
    g1_load_chunk(sb + 1 * ST1_SZ, Ah, Al, Bh, Bl, m0, n0, 1 * KC, tid); CP_COMMIT();

    for (int c = 0; c < NCH2; ++c) {
        if (c + 1 < NCH2) CP_WAIT(1);
        else              CP_WAIT(0);
        __syncthreads();

        uint32_t st = sb + (c & 1) * ST1_SZ;
        uint32_t sAh = st, sAl = st + T_T;
        uint32_t sB0h = st + 2 * T_T, sB0l = st + 3 * T_T;
        uint32_t sB1h = st + 4 * T_T, sB1l = st + 5 * T_T;

#pragma unroll
        for (int ks = 0; ks < 4; ++ks) {
            uint32_t aSegOff = (uint32_t)(((ks * 2 + aSegB) * 16) ^ aXor);
            uint32_t bSegOff = (uint32_t)(((ks * 2 + bSegB) * 16) ^ bXor);
            uint32_t b0h[2][4], b0l[2][4], b1h[2][4], b1l[2][4];
#pragma unroll
            for (int p = 0; p < 2; ++p) {
                uint32_t off = bBase + p * 2048 + bSegOff;
                ldsm4(b0h[p][0], b0h[p][1], b0h[p][2], b0h[p][3], sB0h + off);
                ldsm4(b0l[p][0], b0l[p][1], b0l[p][2], b0l[p][3], sB0l + off);
                ldsm4(b1h[p][0], b1h[p][1], b1h[p][2], b1h[p][3], sB1h + off);
                ldsm4(b1l[p][0], b1l[p][1], b1l[p][2], b1l[p][3], sB1l + off);
            }
#pragma unroll
            for (int mt = 0; mt < 4; ++mt) {
                uint32_t ah[4], al[4];
                uint32_t off = aBase + mt * 2048 + aSegOff;
                ldsm4(ah[0], ah[1], ah[2], ah[3], sAh + off);
                ldsm4(al[0], al[1], al[2], al[3], sAl + off);
#pragma unroll
                for (int nt = 0; nt < 4; ++nt) {
                    const uint32_t* p0h = &b0h[nt >> 1][(nt & 1) * 2];
                    const uint32_t* p0l = &b0l[nt >> 1][(nt & 1) * 2];
                    const uint32_t* p1h = &b1h[nt >> 1][(nt & 1) * 2];
                    const uint32_t* p1l = &b1l[nt >> 1][(nt & 1) * 2];
                    mma16816(acc0[mt][nt], ah, p0h);
                    mma16816(acc0[mt][nt], ah, p0l);
                    mma16816(acc0[mt][nt], al, p0h);
                    mma16816(acc1[mt][nt], ah, p1h);
                    mma16816(acc1[mt][nt], ah, p1l);
                    mma16816(acc1[mt][nt], al, p1h);
                }
            }
        }
        __syncthreads();
        if (c + 2 < NCH2) {
            g1_load_chunk(sb + (c & 1) * ST1_SZ, Ah, Al, Bh, Bl,
                          m0, n0, (c + 2) * KC, tid);
        }
        CP_COMMIT();
    }

#pragma unroll
    for (int mt = 0; mt < 4; ++mt)
#pragma unroll
        for (int nt = 0; nt < 4; ++nt) {
#pragma unroll
            for (int h = 0; h < 2; ++h) {
                int row = m0 + wm * 64 + mt * 16 + (lane >> 2) + h * 8;
                int col = n0 + wn * 32 + nt * 8 + (lane & 3) * 2;
                float v0 = acc0[mt][nt][h * 2 + 0];
                float v1 = acc0[mt][nt][h * 2 + 1];
                float u0 = acc1[mt][nt][h * 2 + 0];
                float u1 = acc1[mt][nt][h * 2 + 1];
                size_t o = (size_t)(2 * row + par) * HM + col;
                __nv_bfloat16 h0, l0, h1, l1;
                bf16split(v0 + u0, h0, l0); bf16split(v1 + u1, h1, l1);
                __nv_bfloat162 hp, lp;
                hp.x = h0; hp.y = h1; lp.x = l0; lp.y = l1;
                *(__nv_bfloat162*)&g_Ash[o] = hp;
                *(__nv_bfloat162*)&g_Asl[o] = lp;
                bf16split(v0 - u0, h0, l0); bf16split(v1 - u1, h1, l1);
                hp.x = h0; hp.y = h1; lp.x = l0; lp.y = l1;
                *(__nv_bfloat162*)&g_Aah[o] = hp;
                *(__nv_bfloat162*)&g_Aal[o] = lp;
            }
        }
}

// ------------------------- gemm2 (K=1024) ----------------------------------
#define ST_SZ   (4 * T_T)
#define STAGES  3
#define SM_G2   (STAGES * ST_SZ)

__device__ __forceinline__ void g2_load_chunk(
    uint32_t st,
    const __nv_bfloat16* __restrict__ Ah, const __nv_bfloat16* __restrict__ Al,
    const __nv_bfloat16* __restrict__ Bh, const __nv_bfloat16* __restrict__ Bl,
    int m0, int n0, int k0, int tid)
{
#pragma unroll
    for (int t = 0; t < 16; ++t) {
        int idx  = tid + t * 256;
        int tile = idx >> 10;
        int r    = (idx >> 3) & 127;
        int seg  = idx & 7;
        const __nv_bfloat16* src;
        int rb;
        if      (tile == 0) { src = Ah; rb = m0; }
        else if (tile == 1) { src = Al; rb = m0; }
        else if (tile == 2) { src = Bh; rb = n0; }
        else                { src = Bl; rb = n0; }
        cp16(st + tile * T_T + sw128(r * 128 + seg * 16),
             src + (size_t)(rb + r) * HM + k0 + seg * 8);
    }
}

__global__ __launch_bounds__(256, 1) void gemm2_kernel(
    const __nv_bfloat16* __restrict__ Bh0, const __nv_bfloat16* __restrict__ Bl0,
    const __nv_bfloat16* __restrict__ Bh1, const __nv_bfloat16* __restrict__ Bl1)
{
    extern __shared__ char smem[];
    uint32_t sb = smem_u32(smem);
    int tid = threadIdx.x, wid = tid >> 5, lane = tid & 31;
    int m0 = blockIdx.y * 128, n0 = blockIdx.x * 128;
    int par = blockIdx.z;
    int wm = wid & 1, wn = wid >> 1;

    const __nv_bfloat16* Ah = par ? g_Aah : g_Ash;
    const __nv_bfloat16* Al = par ? g_Aal : g_Asl;
    const __nv_bfloat16* Bh = par ? Bh1 : Bh0;
    const __nv_bfloat16* Bl = par ? Bl1 : Bl0;

    float acc[4][4][4];
#pragma unroll
    for (int i = 0; i < 4; i++)
#pragma unroll
        for (int j = 0; j < 4; j++)
#pragma unroll
            for (int q = 0; q < 4; q++) acc[i][j][q] = 0.0f;

    int aRow  = wm * 64 + (lane & 7) + ((lane >> 3) & 1) * 8;
    int aSegB = lane >> 4;
    uint32_t aXor  = (uint32_t)(aRow & 7) << 4;
    uint32_t aBase = (uint32_t)aRow * 128;
    int bRow  = wn * 32 + (lane & 7) + ((lane >> 4) & 1) * 8;
    int bSegB = (lane >> 3) & 1;
    uint32_t bXor  = (uint32_t)(bRow & 7) << 4;
    uint32_t bBase = (uint32_t)bRow * 128;

    g2_load_chunk(sb + 0 * ST_SZ, Ah, Al, Bh, Bl, m0, n0, 0 * KC, tid); CP_COMMIT();
    g2_load_chunk(sb + 1 * ST_SZ, Ah, Al, Bh, Bl, m0, n0, 1 * KC, tid); CP_COMMIT();
    g2_load_chunk(sb + 2 * ST_SZ, Ah, Al, Bh, Bl, m0, n0, 2 * KC, tid); CP_COMMIT();

    for (int c = 0; c < NCH2; ++c) {
        if      (c <= NCH2 - 3) CP_WAIT(2);
        else if (c == NCH2 - 2) CP_WAIT(1);
        else                    CP_WAIT(0);
        __syncthreads();

        uint32_t st = sb + (c % STAGES) * ST_SZ;
        uint32_t sAh = st, sAl = st + T_T, sBh = st + 2 * T_T, sBl = st + 3 * T_T;

#pragma unroll
        for (int ks = 0; ks < 4; ++ks) {
            uint32_t ah[4][4], al[4][4], bh[2][4], bl[2][4];
            uint32_t aSegOff = (uint32_t)(((ks * 2 + aSegB) * 16) ^ aXor);
            uint32_t bSegOff = (uint32_t)(((ks * 2 + bSegB) * 16) ^ bXor);
#pragma unroll
            for (int mt = 0; mt < 4; ++mt) {
                uint32_t off = aBase + mt * 2048 + aSegOff;
                ldsm4(ah[mt][0], ah[mt][1], ah[mt][2], ah[mt][3], sAh + off);
                ldsm4(al[mt][0], al[mt][1], al[mt][2], al[mt][3], sAl + off);
            }
#pragma unroll
            for (int p = 0; p < 2; ++p) {
                uint32_t off = bBase + p * 2048 + bSegOff;
                ldsm4(bh[p][0], bh[p][1], bh[p][2], bh[p][3], sBh + off);
                ldsm4(bl[p][0], bl[p][1], bl[p][2], bl[p][3], sBl + off);
            }
#pragma unroll
            for (int mt = 0; mt < 4; ++mt)
#pragma unroll
                for (int nt = 0; nt < 4; ++nt) {
                    const uint32_t* pbh = &bh[nt >> 1][(nt & 1) * 2];
                    const uint32_t* pbl = &bl[nt >> 1][(nt & 1) * 2];
                    mma16816(acc[mt][nt], ah[mt], pbh);
                    mma16816(acc[mt][nt], ah[mt], pbl);
                    mma16816(acc[mt][nt], al[mt], pbh);
                }
        }
        __syncthreads();
        if (c + STAGES < NCH2) {
            g2_load_chunk(sb + (c % STAGES) * ST_SZ, Ah, Al, Bh, Bl,
                          m0, n0, (c + STAGES) * KC, tid);
        }
        CP_COMMIT();
    }

#pragma unroll
    for (int mt = 0; mt < 4; ++mt)
#pragma unroll
        for (int nt = 0; nt < 4; ++nt) {
#pragma unroll
            for (int h = 0; h < 2; ++h) {
                int row = m0 + wm * 64 + mt * 16 + (lane >> 2) + h * 8;
                int col = n0 + wn * 32 + nt * 8 + (lane & 3) * 2;
                float v0 = acc[mt][nt][h * 2 + 0];
                float v1 = acc[mt][nt][h * 2 + 1];
                size_t o = (size_t)(row + PADB) * PPS + PADB + 2 * col + par;
                g_pad[o]     = v0;
                g_pad[o + 2] = v1;
            }
        }
}

// ------------------------------ tiled radon --------------------------------
// 93x100 fp32 tile (37.2KB, rows 16B-aligned) -> 6 blocks/SM.
#define RSW 100
#define RSH 93
#define RMAGIC 12582912.0f       // 1.5 * 2^23
#define RMAGIC_I 0x4B400000

__device__ __forceinline__ float radon_sample(
    uint32_t cbase, float txm, float tym)
{
    float ux = txm + RMAGIC;
    float uy = tym + RMAGIC;
    float wx = (txm - (ux - RMAGIC)) + 0.5f;
    float wy = (tym - (uy - RMAGIC)) + 0.5f;
    uint32_t addr = cbase + __float_as_uint(uy) * (RSW * 4u)
                          + __float_as_uint(ux) * 4u;
    float s00, s01, s10, s11;
    asm volatile("ld.shared.f32 %0, [%1];"       : "=f"(s00) : "r"(addr));
    asm volatile("ld.shared.f32 %0, [%1+4];"     : "=f"(s01) : "r"(addr));
    asm volatile("ld.shared.f32 %0, [%1+400];"   : "=f"(s10) : "r"(addr));
    asm volatile("ld.shared.f32 %0, [%1+404];"   : "=f"(s11) : "r"(addr));
    float top = fmaf(wx, s01 - s00, s00);
    float bot = fmaf(wx, s11 - s10, s10);
    return fmaf(wy, bot - top, top);
}

__global__ __launch_bounds__(256, 6) void radon_tiled_kernel() {
    __shared__ float sm[RSH * RSW];   // reduction overlays sm[0..255] at end

    int a  = blockIdx.z;
    int x0 = blockIdx.x * 64;
    int y0 = blockIdx.y * 64;
    int tid = threadIdx.x, wid = tid >> 5, lane = tid & 31;

    float ang = (float)(3.141592653589793 * (double)a / 31.0);
    float ca = cosf(ang);
    float sa = sinf(ang);
    const float cen = (float)(PP / 2);
    float c1 = cen * (ca + sa - 1.0f);
    float c2 = cen * (ca - sa - 1.0f);

    float xf0 = (float)x0, xf1 = (float)(x0 + 63);
    float yf0 = (float)y0, yf1 = (float)(y0 + 63);
    float u00 = ca * xf0 + sa * yf0 - c1, u01 = ca * xf0 + sa * yf1 - c1;
    float u10 = ca * xf1 + sa * yf0 - c1, u11 = ca * xf1 + sa * yf1 - c1;
    float v00 = -sa * xf0 + ca * yf0 - c2, v01 = -sa * xf0 + ca * yf1 - c2;
    float v10 = -sa * xf1 + ca * yf0 - c2, v11 = -sa * xf1 + ca * yf1 - c2;
    float umin = fminf(fminf(u00, u01), fminf(u10, u11));
    float umax = fmaxf(fmaxf(u00, u01), fmaxf(u10, u11));
    float vmin = fminf(fminf(v00, v01), fminf(v10, v11));
    float vmax = fmaxf(fmaxf(v00, v01), fmaxf(v10, v11));

    int u0i = (int)floorf(umin) - 1;
    int v0i = (int)floorf(vmin) - 1;
    int W = (int)floorf(umax) + 1 - u0i + 1;   // cols u0i .. floor(umax)+1
    int H = (int)floorf(vmax) + 1 - v0i + 1;   // rows v0i .. floor(vmax)+1

    int u0m = u0i % PP; if (u0m < 0) u0m += PP;
    int v0m = v0i % PP; if (v0m < 0) v0m += PP;

    int sft  = u0m & 3;
    int u0s  = u0i - sft;
    int u0ms = u0m - sft;
    int W4   = (W + sft + 3) & ~3;

    uint32_t smb = smem_u32(sm);
    if (u0ms + W4 <= PP) {
        int nq = W4 >> 2;
        for (int r = wid; r < H; r += 8) {
            int rm = v0m + r; if (rm >= PP) rm -= PP;
            const float* src = g_pad + (size_t)rm * PPS + u0ms;
            uint32_t drow = smb + (uint32_t)(r * RSW) * 4;
            for (int q = lane; q < nq; q += 32)
                cp16(drow + (uint32_t)q * 16, src + q * 4);
        }
    } else {
        for (int r = wid; r < H; r += 8) {
            int rm = v0m + r; if (rm >= PP) rm -= PP;
            const float* rowp = g_pad + (size_t)rm * PPS;
            uint32_t drow = smb + (uint32_t)(r * RSW) * 4;
            for (int c = lane; c < W4; c += 32) {
                int cm = u0ms + c; if (cm >= PP) cm -= PP;
                cp4(drow + (uint32_t)c * 4, rowp + cm);
            }
        }
    }
    CP_COMMIT();

    int xl   = tid & 63;
    int ysub = tid >> 6;
    int x    = x0 + xl;
    float xf = (float)x;
    float bx = ca * xf - c1;
    float by = -sa * xf - c2;

    int ybeg = y0 + ysub * 16;
    float ybf  = (float)ybeg;
    float xin0 = fmaf(sa, ybf, bx);
    float yin0 = fmaf(ca, ybf, by);
    float fx0 = floorf(xin0);
    float fy0 = floorf(yin0);
    float wx0m = (xin0 - fx0) - 0.5f;
    float wy0m = (yin0 - fy0) - 0.5f;
    int   base0 = ((int)fy0 - v0i) * RSW + ((int)fx0 - u0s);
    uint32_t cbase = smb + (uint32_t)base0 * 4u
                   - (uint32_t)RMAGIC_I * (RSW * 4u)
                   - (uint32_t)RMAGIC_I * 4u;

    CP_WAIT(0);
    __syncthreads();

    float acc0 = 0.0f, acc1 = 0.0f;
    if (y0 + 64 <= PP) {
#pragma unroll
        for (int i = 0; i < 16; ++i) {
            float r = radon_sample(cbase,
                                   fmaf((float)i, sa, wx0m),
                                   fmaf((float)i, ca, wy0m));
            if (i & 1) acc1 += r; else acc0 += r;
        }
    } else {
#pragma unroll
        for (int i = 0; i < 16; ++i) {
            float r = radon_sample(cbase,
                                   fmaf((float)i, sa, wx0m),
                                   fmaf((float)i, ca, wy0m));
            float g = (ybeg + i < PP) ? 1.0f : 0.0f;
            if (i & 1) acc1 = fmaf(g, r, acc1);
            else       acc0 = fmaf(g, r, acc0);
        }
    }
    float acc = acc0 + acc1;

    __syncthreads();
    sm[ysub * 64 + xl] = acc;
    __syncthreads();
    if (tid < 64) {
        float s = ((sm[tid] + sm[64 + tid]) + sm[128 + tid]) + sm[192 + tid];
        int xo = x0 + tid;
        if (xo < PP)
            g_lpart[(size_t)blockIdx.y * TOT + a * PP + xo] = s;
    }
}

// --------------------------- reduce / normalize ----------------------------
__global__ void reduce_max_kernel() {
    __shared__ float smax[256];
    int idx = blockIdx.x * 256 + threadIdx.x;
    float v = -__int_as_float(0x7f800000);
    if (idx < TOT) {
        float s = 0.0f;
        for (int p = 0; p < NYT; p++) s += g_lpart[(size_t)p * TOT + idx];
        g_lines[idx] = s;
        v = s;
    }
    smax[threadIdx.x] = v;
    __syncthreads();
    for (int o = 128; o > 0; o >>= 1) {
        if (threadIdx.x < o)
            smax[threadIdx.x] = fmaxf(smax[threadIdx.x], smax[threadIdx.x + o]);
        __syncthreads();
    }
    if (threadIdx.x == 0) {
        unsigned u = __float_as_uint(smax[0]);
        unsigned enc = (u & 0x80000000u) ? ~u : (u | 0x80000000u);
        atomicMax(&g_maxbits, enc);
    }
}

__global__ void normalize_kernel(float* __restrict__ out) {
    int idx = blockIdx.x * 256 + threadIdx.x;
    if (idx >= TOT) return;
    unsigned u = g_maxbits;
    float mx = (u & 0x80000000u) ? __uint_as_float(u & 0x7fffffffu)
                                 : __uint_as_float(~u);
    int x = idx >> 5;
    int a = idx & 31;
    out[idx] = g_lines[a * PP + x] / mx;
}

// ---------------------------------------------------------------------------
extern "C" void kernel_launch(void* const* d_in, const int* in_sizes, int n_in,
                              void* d_out, int out_size) {
    const float* img = (const float*)d_in[0];
    float* out = (float*)d_out;

    static int s_init = 0;
    if (!s_init) {
        cudaFuncSetAttribute(gemm1_kernel,
                             cudaFuncAttributeMaxDynamicSharedMemorySize, SM_G1);
        cudaFuncSetAttribute(gemm2_kernel,
                             cudaFuncAttributeMaxDynamicSharedMemorySize, SM_G2);
        cudaFuncSetAttribute(radon_tiled_kernel,
                             cudaFuncAttributePreferredSharedMemoryCarveout, 100);
        s_init = 1;
    }

    prep_kernel<<<NBB + NCG + NTS, 256>>>(img);

    __nv_bfloat16 *pCeh, *pCel, *pCoh, *pCol;
    cudaGetSymbolAddress((void**)&pCeh, g_Ceh);
    cudaGetSymbolAddress((void**)&pCel, g_Cel);
    cudaGetSymbolAddress((void**)&pCoh, g_Coh);
    cudaGetSymbolAddress((void**)&pCol, g_Col);

    dim3 g1(HM / 128, HM / 128, 2);
    gemm1_kernel<<<g1, 256, SM_G1>>>(pCeh, pCel, pCoh, pCol);

    dim3 g2(HM / 128, MM / 128, 2);
    gemm2_kernel<<<g2, 256, SM_G2>>>(pCeh, pCel, pCoh, pCol);

    dim3 rg(NXT, NYT, NANG);
    radon_tiled_kernel<<<rg, 256>>>();

    reduce_max_kernel<<<(TOT + 255) / 256, 256>>>();
    normalize_kernel<<<(TOT + 255) / 256, 256>>>(out);
}

// round 17
// speedup vs baseline: 1.4063x; 1.0046x over previous
#include <cuda_runtime.h>
#include <cuda_bf16.h>
#include <cstdint>

// ---------------------------------------------------------------------------
// image_prj: D = dct2(image) [2048x2048, ortho] -> pad to 2198x2198 ->
// 32-angle radon (bilinear, WRAP) -> lines^T / max
// GEMMs: DCT even/odd fold; gemm1 emits folded A directly (128x128 tiles);
// gemm2 256x128 tiles (single wave, no tail). Radon: cp.async 93x100 tile,
// 6 blocks/SM, bias-round bilinear.
// ---------------------------------------------------------------------------

#define MM    2048
#define HM    1024
#define PP    2198
#define PPS   2200
#define PADB  75
#define NANG  32
#define TOT   (NANG * PP)
#define NYT   35
#define NXT   35

__device__ __nv_bfloat16 g_Ceh[HM * HM], g_Cel[HM * HM];   // C even rows
__device__ __nv_bfloat16 g_Coh[HM * HM], g_Col[HM * HM];   // C odd rows
__device__ __nv_bfloat16 g_Bsh[MM * HM], g_Bsl[MM * HM];   // X^T fold-sum
__device__ __nv_bfloat16 g_Bah[MM * HM], g_Bal[MM * HM];   // X^T fold-diff
__device__ __nv_bfloat16 g_Ash[MM * HM], g_Asl[MM * HM];   // tmp fold-sum
__device__ __nv_bfloat16 g_Aah[MM * HM], g_Aal[MM * HM];   // tmp fold-diff
__device__ float    g_pad[PP * PPS];
__device__ float    g_lpart[NYT * TOT];
__device__ float    g_lines[TOT];
__device__ unsigned g_maxbits;

// ------------------------------ PTX helpers -------------------------------
__device__ __forceinline__ uint32_t smem_u32(const void* p) {
    uint32_t a;
    asm("{ .reg .u64 t; cvta.to.shared.u64 t, %1; cvt.u32.u64 %0, t; }"
        : "=r"(a) : "l"(p));
    return a;
}
#define CP_COMMIT() asm volatile("cp.async.commit_group;" ::: "memory")
#define CP_WAIT(n)  asm volatile("cp.async.wait_group %0;" :: "n"(n) : "memory")

__device__ __forceinline__ void cp16(uint32_t dst, const void* src) {
    asm volatile("cp.async.cg.shared.global [%0], [%1], 16;"
                 :: "r"(dst), "l"(src) : "memory");
}
__device__ __forceinline__ void cp4(uint32_t dst, const void* src) {
    asm volatile("cp.async.ca.shared.global [%0], [%1], 4;"
                 :: "r"(dst), "l"(src) : "memory");
}
__device__ __forceinline__ void ldsm4(uint32_t& r0, uint32_t& r1,
                                      uint32_t& r2, uint32_t& r3, uint32_t a) {
    asm volatile("ldmatrix.sync.aligned.m8n8.x4.shared.b16 {%0,%1,%2,%3}, [%4];"
                 : "=r"(r0), "=r"(r1), "=r"(r2), "=r"(r3) : "r"(a));
}
__device__ __forceinline__ void mma16816(float* d, const uint32_t* a,
                                         const uint32_t* b) {
    asm volatile("mma.sync.aligned.m16n8k16.row.col.f32.bf16.bf16.f32 "
                 "{%0,%1,%2,%3}, {%4,%5,%6,%7}, {%8,%9}, {%0,%1,%2,%3};"
                 : "+f"(d[0]), "+f"(d[1]), "+f"(d[2]), "+f"(d[3])
                 : "r"(a[0]), "r"(a[1]), "r"(a[2]), "r"(a[3]),
                   "r"(b[0]), "r"(b[1]));
}
__device__ __forceinline__ uint32_t sw128(uint32_t b) { return b ^ ((b >> 3) & 0x70); }
__device__ __forceinline__ void bf16split(float v, __nv_bfloat16& h, __nv_bfloat16& l) {
    h = __float2bfloat16(v);
    l = __float2bfloat16(v - __bfloat162float(h));
}

// --------------------------- merged prep kernel ----------------------------
#define NB1 (150 * PP)
#define NB2 (MM * 150)
#define NBB ((NB1 + NB2 + 255) / 256)
#define NCG (2 * HM * HM / 256)
#define NTS ((HM / 32) * (MM / 32))

__global__ void prep_kernel(const float* __restrict__ img) {
    __shared__ float ts[32][33];
    __shared__ float ta[32][33];
    int b = blockIdx.x;
    int tid = threadIdx.x;

    if (b < NBB) {
        int idx = b * 256 + tid;
        if (idx == 0) g_maxbits = 0u;
        if (idx < NB1) {
            int r = idx / PP, c = idx % PP;
            int row = (r < 75) ? r : (2123 + r - 75);
            g_pad[(size_t)row * PPS + c] = 0.0f;
        } else if (idx < NB1 + NB2) {
            int j = idx - NB1;
            int r = j / 150, c = j % 150;
            int col = (c < 75) ? c : (2123 + c - 75);
            g_pad[(size_t)(75 + r) * PPS + col] = 0.0f;
        }
        return;
    }
    b -= NBB;
    if (b < NCG) {
        int idx = b * 256 + tid;
        int par = idx >> 20;
        int mp  = (idx >> 10) & (HM - 1);
        int n   = idx & (HM - 1);
        int k   = 2 * mp + par;
        int r   = ((2 * n + 1) * k) & (4 * MM - 1);
        float t = (float)r * (1.0f / (2.0f * MM));
        float c = cospif(t);
        float s = (k == 0) ? 0.022097086912079608f : 0.03125f;
        float v = s * c;
        __nv_bfloat16 h, l; bf16split(v, h, l);
        size_t o = (size_t)mp * HM + n;
        if (par) { g_Coh[o] = h; g_Col[o] = l; }
        else     { g_Ceh[o] = h; g_Cel[o] = l; }
        return;
    }
    b -= NCG;
    {
        int kt = b & 31, nt = b >> 5;
        int kb = kt * 32, nb = nt * 32;
        int tx = tid & 31, ty = tid >> 5;
#pragma unroll
        for (int i = 0; i < 4; i++) {
            int k = kb + ty + i * 8;
            float v1 = img[(size_t)k * MM + nb + tx];
            float v2 = img[(size_t)(MM - 1 - k) * MM + nb + tx];
            ts[ty + i * 8][tx] = v1 + v2;
            ta[ty + i * 8][tx] = v1 - v2;
        }
        __syncthreads();
#pragma unroll
        for (int i = 0; i < 4; i++) {
            int nl = ty + i * 8;
            size_t o = (size_t)(nb + nl) * HM + kb + tx;
            __nv_bfloat16 h, l;
            bf16split(ts[tx][nl], h, l); g_Bsh[o] = h; g_Bsl[o] = l;
            bf16split(ta[tx][nl], h, l); g_Bah[o] = h; g_Bal[o] = l;
        }
    }
}

// --------------------- gemm1: mirror-pair, fold-emitting --------------------
#define KC      64
#define NCH2    (HM / KC)          // 16
#define T_T     16384
#define ST1_SZ  (6 * T_T)          // 96KB
#define SM_G1   (2 * ST1_SZ)       // 192KB

__device__ __forceinline__ void g1_load_chunk(
    uint32_t st,
    const __nv_bfloat16* __restrict__ Ah, const __nv_bfloat16* __restrict__ Al,
    const __nv_bfloat16* __restrict__ Bh, const __nv_bfloat16* __restrict__ Bl,
    int m0, int n0, int k0, int tid)
{
#pragma unroll
    for (int t = 0; t < 24; ++t) {
        int idx  = tid + t * 256;
        int tile = idx >> 10;
        int r    = (idx >> 3) & 127;
        int seg  = idx & 7;
        const __nv_bfloat16* src;
        int row;
        switch (tile) {
            case 0: src = Ah; row = m0 + r; break;
            case 1: src = Al; row = m0 + r; break;
            case 2: src = Bh; row = n0 + r; break;
            case 3: src = Bl; row = n0 + r; break;
            case 4: src = Bh; row = MM - 1 - n0 - r; break;
            default: src = Bl; row = MM - 1 - n0 - r; break;
        }
        cp16(st + tile * T_T + sw128(r * 128 + seg * 16),
             src + (size_t)row * HM + k0 + seg * 8);
    }
}

__global__ __launch_bounds__(256, 1) void gemm1_kernel(
    const __nv_bfloat16* __restrict__ Ah0, const __nv_bfloat16* __restrict__ Al0,
    const __nv_bfloat16* __restrict__ Ah1, const __nv_bfloat16* __restrict__ Al1)
{
    extern __shared__ char smem[];
    uint32_t sb = smem_u32(smem);
    int tid = threadIdx.x, wid = tid >> 5, lane = tid & 31;
    int m0 = blockIdx.y * 128, n0 = blockIdx.x * 128;
    int par = blockIdx.z;
    int wm = wid & 1, wn = wid >> 1;

    const __nv_bfloat16* Ah = par ? Ah1 : Ah0;
    const __nv_bfloat16* Al = par ? Al1 : Al0;
    const __nv_bfloat16* Bh = par ? g_Bah : g_Bsh;
    const __nv_bfloat16* Bl = par ? g_Bal : g_Bsl;

    float acc0[4][4][4], acc1[4][4][4];
#pragma unroll
    for (int i = 0; i < 4; i++)
#pragma unroll
        for (int j = 0; j < 4; j++)
#pragma unroll
            for (int q = 0; q < 4; q++) { acc0[i][j][q] = 0.0f; acc1[i][j][q] = 0.0f; }

    int aRow  = wm * 64 + (lane & 7) + ((lane >> 3) & 1) * 8;
    int aSegB = lane >> 4;
    uint32_t aXor  = (uint32_t)(aRow & 7) << 4;
    uint32_t aBase = (uint32_t)aRow * 128;
    int bRow  = wn * 32 + (lane & 7) + ((lane >> 4) & 1) * 8;
    int bSegB = (lane >> 3) & 1;
    uint32_t bXor  = (uint32_t)(bRow & 7) << 4;
    uint32_t bBase = (uint32_t)bRow * 128;

    g1_load_chunk(sb + 0 * ST1_SZ, Ah, Al, Bh, Bl, m0, n0, 0 * KC, tid); CP_COMMIT();
    g1_load_chunk(sb + 1 * ST1_SZ, Ah, Al, Bh, Bl, m0, n0, 1 * KC, tid); CP_COMMIT();

    for (int c = 0; c < NCH2; ++c) {
        if (c + 1 < NCH2) CP_WAIT(1);
        else              CP_WAIT(0);
        __syncthreads();

        uint32_t st = sb + (c & 1) * ST1_SZ;
        uint32_t sAh = st, sAl = st + T_T;
        uint32_t sB0h = st + 2 * T_T, sB0l = st + 3 * T_T;
        uint32_t sB1h = st + 4 * T_T, sB1l = st + 5 * T_T;

#pragma unroll
        for (int ks = 0; ks < 4; ++ks) {
            uint32_t aSegOff = (uint32_t)(((ks * 2 + aSegB) * 16) ^ aXor);
            uint32_t bSegOff = (uint32_t)(((ks * 2 + bSegB) * 16) ^ bXor);
            uint32_t b0h[2][4], b0l[2][4], b1h[2][4], b1l[2][4];
#pragma unroll
            for (int p = 0; p < 2; ++p) {
                uint32_t off = bBase + p * 2048 + bSegOff;
                ldsm4(b0h[p][0], b0h[p][1], b0h[p][2], b0h[p][3], sB0h + off);
                ldsm4(b0l[p][0], b0l[p][1], b0l[p][2], b0l[p][3], sB0l + off);
                ldsm4(b1h[p][0], b1h[p][1], b1h[p][2], b1h[p][3], sB1h + off);
                ldsm4(b1l[p][0], b1l[p][1], b1l[p][2], b1l[p][3], sB1l + off);
            }
#pragma unroll
            for (int mt = 0; mt < 4; ++mt) {
                uint32_t ah[4], al[4];
                uint32_t off = aBase + mt * 2048 + aSegOff;
                ldsm4(ah[0], ah[1], ah[2], ah[3], sAh + off);
                ldsm4(al[0], al[1], al[2], al[3], sAl + off);
#pragma unroll
                for (int nt = 0; nt < 4; ++nt) {
                    const uint32_t* p0h = &b0h[nt >> 1][(nt & 1) * 2];
                    const uint32_t* p0l = &b0l[nt >> 1][(nt & 1) * 2];
                    const uint32_t* p1h = &b1h[nt >> 1][(nt & 1) * 2];
                    const uint32_t* p1l = &b1l[nt >> 1][(nt & 1) * 2];
                    mma16816(acc0[mt][nt], ah, p0h);
                    mma16816(acc0[mt][nt], ah, p0l);
                    mma16816(acc0[mt][nt], al, p0h);
                    mma16816(acc1[mt][nt], ah, p1h);
                    mma16816(acc1[mt][nt], ah, p1l);
                    mma16816(acc1[mt][nt], al, p1h);
                }
            }
        }
        __syncthreads();
        if (c + 2 < NCH2) {
            g1_load_chunk(sb + (c & 1) * ST1_SZ, Ah, Al, Bh, Bl,
                          m0, n0, (c + 2) * KC, tid);
        }
        CP_COMMIT();
    }

#pragma unroll
    for (int mt = 0; mt < 4; ++mt)
#pragma unroll
        for (int nt = 0; nt < 4; ++nt) {
#pragma unroll
            for (int h = 0; h < 2; ++h) {
                int row = m0 + wm * 64 + mt * 16 + (lane >> 2) + h * 8;
                int col = n0 + wn * 32 + nt * 8 + (lane & 3) * 2;
                float v0 = acc0[mt][nt][h * 2 + 0];
                float v1 = acc0[mt][nt][h * 2 + 1];
                float u0 = acc1[mt][nt][h * 2 + 0];
                float u1 = acc1[mt][nt][h * 2 + 1];
                size_t o = (size_t)(2 * row + par) * HM + col;
                __nv_bfloat16 h0, l0, h1, l1;
                bf16split(v0 + u0, h0, l0); bf16split(v1 + u1, h1, l1);
                __nv_bfloat162 hp, lp;
                hp.x = h0; hp.y = h1; lp.x = l0; lp.y = l1;
                *(__nv_bfloat162*)&g_Ash[o] = hp;
                *(__nv_bfloat162*)&g_Asl[o] = lp;
                bf16split(v0 - u0, h0, l0); bf16split(v1 - u1, h1, l1);
                hp.x = h0; hp.y = h1; lp.x = l0; lp.y = l1;
                *(__nv_bfloat162*)&g_Aah[o] = hp;
                *(__nv_bfloat162*)&g_Aal[o] = lp;
            }
        }
}

// ---------------- gemm2: 256x128 CTA tile, single wave ---------------------
#define TA2     32768              // A split tile: 256 rows x 128B
#define TB2     16384              // B split tile: 128 rows x 128B
#define ST2_SZ  (2 * TA2 + 2 * TB2)   // 96KB
#define SM_G2   (2 * ST2_SZ)          // 192KB

__device__ __forceinline__ void g2_load_chunk(
    uint32_t st,
    const __nv_bfloat16* __restrict__ Ah, const __nv_bfloat16* __restrict__ Al,
    const __nv_bfloat16* __restrict__ Bh, const __nv_bfloat16* __restrict__ Bl,
    int m0, int n0, int k0, int tid)
{
#pragma unroll
    for (int t = 0; t < 24; ++t) {
        int idx = tid + t * 256;
        if (idx < 4096) {                       // A hi/lo: 2 x 256 rows x 8 segs
            int sp  = idx >> 11;
            int r   = (idx >> 3) & 255;
            int seg = idx & 7;
            const __nv_bfloat16* src = sp ? Al : Ah;
            cp16(st + sp * TA2 + sw128(r * 128 + seg * 16),
                 src + (size_t)(m0 + r) * HM + k0 + seg * 8);
        } else {                                // B hi/lo: 2 x 128 rows x 8 segs
            int j   = idx - 4096;
            int sp  = j >> 10;
            int r   = (j >> 3) & 127;
            int seg = j & 7;
            const __nv_bfloat16* src = sp ? Bl : Bh;
            cp16(st + 2 * TA2 + sp * TB2 + sw128(r * 128 + seg * 16),
                 src + (size_t)(n0 + r) * HM + k0 + seg * 8);
        }
    }
}

__global__ __launch_bounds__(256, 1) void gemm2_kernel(
    const __nv_bfloat16* __restrict__ Bh0, const __nv_bfloat16* __restrict__ Bl0,
    const __nv_bfloat16* __restrict__ Bh1, const __nv_bfloat16* __restrict__ Bl1)
{
    extern __shared__ char smem[];
    uint32_t sb = smem_u32(smem);
    int tid = threadIdx.x, wid = tid >> 5, lane = tid & 31;
    int m0 = blockIdx.y * 256, n0 = blockIdx.x * 128;
    int par = blockIdx.z;
    int wm = wid >> 1, wn = wid & 1;       // 4(m) x 2(n), warp tile 64x64

    const __nv_bfloat16* Ah = par ? g_Aah : g_Ash;
    const __nv_bfloat16* Al = par ? g_Aal : g_Asl;
    const __nv_bfloat16* Bh = par ? Bh1 : Bh0;
    const __nv_bfloat16* Bl = par ? Bl1 : Bl0;

    float acc[4][8][4];
#pragma unroll
    for (int i = 0; i < 4; i++)
#pragma unroll
        for (int j = 0; j < 8; j++)
#pragma unroll
            for (int q = 0; q < 4; q++) acc[i][j][q] = 0.0f;

    int aRow  = wm * 64 + (lane & 7) + ((lane >> 3) & 1) * 8;
    int aSegB = lane >> 4;
    uint32_t aXor  = (uint32_t)(aRow & 7) << 4;
    uint32_t aBase = (uint32_t)aRow * 128;
    int bRow  = wn * 64 + (lane & 7) + ((lane >> 4) & 1) * 8;
    int bSegB = (lane >> 3) & 1;
    uint32_t bXor  = (uint32_t)(bRow & 7) << 4;
    uint32_t bBase = (uint32_t)bRow * 128;

    g2_load_chunk(sb + 0 * ST2_SZ, Ah, Al, Bh, Bl, m0, n0, 0 * KC, tid); CP_COMMIT();
    g2_load_chunk(sb + 1 * ST2_SZ, Ah, Al, Bh, Bl, m0, n0, 1 * KC, tid); CP_COMMIT();

    for (int c = 0; c < NCH2; ++c) {
        if (c + 1 < NCH2) CP_WAIT(1);
        else              CP_WAIT(0);
        __syncthreads();

        uint32_t st = sb + (c & 1) * ST2_SZ;
        uint32_t sAh = st, sAl = st + TA2;
        uint32_t sBh = st + 2 * TA2, sBl = st + 2 * TA2 + TB2;

#pragma unroll
        for (int ks = 0; ks < 4; ++ks) {
            uint32_t aSegOff = (uint32_t)(((ks * 2 + aSegB) * 16) ^ aXor);
            uint32_t bSegOff = (uint32_t)(((ks * 2 + bSegB) * 16) ^ bXor);
            uint32_t bh[4][4], bl[4][4];
#pragma unroll
            for (int p = 0; p < 4; ++p) {
                uint32_t off = bBase + p * 2048 + bSegOff;
                ldsm4(bh[p][0], bh[p][1], bh[p][2], bh[p][3], sBh + off);
                ldsm4(bl[p][0], bl[p][1], bl[p][2], bl[p][3], sBl + off);
            }
#pragma unroll
            for (int mt = 0; mt < 4; ++mt) {
                uint32_t ah[4], al[4];
                uint32_t off = aBase + mt * 2048 + aSegOff;
                ldsm4(ah[0], ah[1], ah[2], ah[3], sAh + off);
                ldsm4(al[0], al[1], al[2], al[3], sAl + off);
#pragma unroll
                for (int nt = 0; nt < 8; ++nt) {
                    const uint32_t* pbh = &bh[nt >> 1][(nt & 1) * 2];
                    const uint32_t* pbl = &bl[nt >> 1][(nt & 1) * 2];
                    mma16816(acc[mt][nt], ah, pbh);
                    mma16816(acc[mt][nt], ah, pbl);
                    mma16816(acc[mt][nt], al, pbh);
                }
            }
        }
        __syncthreads();
        if (c + 2 < NCH2)
            g2_load_chunk(sb + (c & 1) * ST2_SZ, Ah, Al, Bh, Bl,
                          m0, n0, (c + 2) * KC, tid);
        CP_COMMIT();
    }

#pragma unroll
    for (int mt = 0; mt < 4; ++mt)
#pragma unroll
        for (int nt = 0; nt < 8; ++nt) {
#pragma unroll
            for (int h = 0; h < 2; ++h) {
                int row = m0 + wm * 64 + mt * 16 + (lane >> 2) + h * 8;
                int col = n0 + wn * 64 + nt * 8 + (lane & 3) * 2;
                float v0 = acc[mt][nt][h * 2 + 0];
                float v1 = acc[mt][nt][h * 2 + 1];
                size_t o = (size_t)(row + PADB) * PPS + PADB + 2 * col + par;
                g_pad[o]     = v0;
                g_pad[o + 2] = v1;
            }
        }
}

// ------------------------------ tiled radon --------------------------------
// 93x100 fp32 tile (37.2KB, rows 16B-aligned) -> 6 blocks/SM.
#define RSW 100
#define RSH 93
#define RMAGIC 12582912.0f       // 1.5 * 2^23
#define RMAGIC_I 0x4B400000

__device__ __forceinline__ float radon_sample(
    uint32_t cbase, float txm, float tym)
{
    float ux = txm + RMAGIC;
    float uy = tym + RMAGIC;
    float wx = (txm - (ux - RMAGIC)) + 0.5f;
    float wy = (tym - (uy - RMAGIC)) + 0.5f;
    uint32_t addr = cbase + __float_as_uint(uy) * (RSW * 4u)
                          + __float_as_uint(ux) * 4u;
    float s00, s01, s10, s11;
    asm volatile("ld.shared.f32 %0, [%1];"       : "=f"(s00) : "r"(addr));
    asm volatile("ld.shared.f32 %0, [%1+4];"     : "=f"(s01) : "r"(addr));
    asm volatile("ld.shared.f32 %0, [%1+400];"   : "=f"(s10) : "r"(addr));
    asm volatile("ld.shared.f32 %0, [%1+404];"   : "=f"(s11) : "r"(addr));
    float top = fmaf(wx, s01 - s00, s00);
    float bot = fmaf(wx, s11 - s10, s10);
    return fmaf(wy, bot - top, top);
}

__global__ __launch_bounds__(256, 6) void radon_tiled_kernel() {
    __shared__ float sm[RSH * RSW];

    int a  = blockIdx.z;
    int x0 = blockIdx.x * 64;
    int y0 = blockIdx.y * 64;
    int tid = threadIdx.x, wid = tid >> 5, lane = tid & 31;

    float ang = (float)(3.141592653589793 * (double)a / 31.0);
    float ca = cosf(ang);
    float sa = sinf(ang);
    const float cen = (float)(PP / 2);
    float c1 = cen * (ca + sa - 1.0f);
    float c2 = cen * (ca - sa - 1.0f);

    float xf0 = (float)x0, xf1 = (float)(x0 + 63);
    float yf0 = (float)y0, yf1 = (float)(y0 + 63);
    float u00 = ca * xf0 + sa * yf0 - c1, u01 = ca * xf0 + sa * yf1 - c1;
    float u10 = ca * xf1 + sa * yf0 - c1, u11 = ca * xf1 + sa * yf1 - c1;
    float v00 = -sa * xf0 + ca * yf0 - c2, v01 = -sa * xf0 + ca * yf1 - c2;
    float v10 = -sa * xf1 + ca * yf0 - c2, v11 = -sa * xf1 + ca * yf1 - c2;
    float umin = fminf(fminf(u00, u01), fminf(u10, u11));
    float umax = fmaxf(fmaxf(u00, u01), fmaxf(u10, u11));
    float vmin = fminf(fminf(v00, v01), fminf(v10, v11));
    float vmax = fmaxf(fmaxf(v00, v01), fmaxf(v10, v11));

    int u0i = (int)floorf(umin) - 1;
    int v0i = (int)floorf(vmin) - 1;
    int W = (int)floorf(umax) + 1 - u0i + 1;
    int H = (int)floorf(vmax) + 1 - v0i + 1;

    int u0m = u0i % PP; if (u0m < 0) u0m += PP;
    int v0m = v0i % PP; if (v0m < 0) v0m += PP;

    int sft  = u0m & 3;
    int u0s  = u0i - sft;
    int u0ms = u0m - sft;
    int W4   = (W + sft + 3) & ~3;

    uint32_t smb = smem_u32(sm);
    if (u0ms + W4 <= PP) {
        int nq = W4 >> 2;
        for (int r = wid; r < H; r += 8) {
            int rm = v0m + r; if (rm >= PP) rm -= PP;
            const float* src = g_pad + (size_t)rm * PPS + u0ms;
            uint32_t drow = smb + (uint32_t)(r * RSW) * 4;
            for (int q = lane; q < nq; q += 32)
                cp16(drow + (uint32_t)q * 16, src + q * 4);
        }
    } else {
        for (int r = wid; r < H; r += 8) {
            int rm = v0m + r; if (rm >= PP) rm -= PP;
            const float* rowp = g_pad + (size_t)rm * PPS;
            uint32_t drow = smb + (uint32_t)(r * RSW) * 4;
            for (int c = lane; c < W4; c += 32) {
                int cm = u0ms + c; if (cm >= PP) cm -= PP;
                cp4(drow + (uint32_t)c * 4, rowp + cm);
            }
        }
    }
    CP_COMMIT();

    int xl   = tid & 63;
    int ysub = tid >> 6;
    int x    = x0 + xl;
    float xf = (float)x;
    float bx = ca * xf - c1;
    float by = -sa * xf - c2;

    int ybeg = y0 + ysub * 16;
    float ybf  = (float)ybeg;
    float xin0 = fmaf(sa, ybf, bx);
    float yin0 = fmaf(ca, ybf, by);
    float fx0 = floorf(xin0);
    float fy0 = floorf(yin0);
    float wx0m = (xin0 - fx0) - 0.5f;
    float wy0m = (yin0 - fy0) - 0.5f;
    int   base0 = ((int)fy0 - v0i) * RSW + ((int)fx0 - u0s);
    uint32_t cbase = smb + (uint32_t)base0 * 4u
                   - (uint32_t)RMAGIC_I * (RSW * 4u)
                   - (uint32_t)RMAGIC_I * 4u;

    CP_WAIT(0);
    __syncthreads();

    float acc0 = 0.0f, acc1 = 0.0f;
    if (y0 + 64 <= PP) {
#pragma unroll
        for (int i = 0; i < 16; ++i) {
            float r = radon_sample(cbase,
                                   fmaf((float)i, sa, wx0m),
                                   fmaf((float)i, ca, wy0m));
            if (i & 1) acc1 += r; else acc0 += r;
        }
    } else {
#pragma unroll
        for (int i = 0; i < 16; ++i) {
            float r = radon_sample(cbase,
                                   fmaf((float)i, sa, wx0m),
                                   fmaf((float)i, ca, wy0m));
            float g = (ybeg + i < PP) ? 1.0f : 0.0f;
            if (i & 1) acc1 = fmaf(g, r, acc1);
            else       acc0 = fmaf(g, r, acc0);
        }
    }
    float acc = acc0 + acc1;

    __syncthreads();
    sm[ysub * 64 + xl] = acc;
    __syncthreads();
    if (tid < 64) {
        float s = ((sm[tid] + sm[64 + tid]) + sm[128 + tid]) + sm[192 + tid];
        int xo = x0 + tid;
        if (xo < PP)
            g_lpart[(size_t)blockIdx.y * TOT + a * PP + xo] = s;
    }
}

// --------------------------- reduce / normalize ----------------------------
__global__ void reduce_max_kernel() {
    __shared__ float smax[256];
    int idx = blockIdx.x * 256 + threadIdx.x;
    float v = -__int_as_float(0x7f800000);
    if (idx < TOT) {
        float s = 0.0f;
        for (int p = 0; p < NYT; p++) s += g_lpart[(size_t)p * TOT + idx];
        g_lines[idx] = s;
        v = s;
    }
    smax[threadIdx.x] = v;
    __syncthreads();
    for (int o = 128; o > 0; o >>= 1) {
        if (threadIdx.x < o)
            smax[threadIdx.x] = fmaxf(smax[threadIdx.x], smax[threadIdx.x + o]);
        __syncthreads();
    }
    if (threadIdx.x == 0) {
        unsigned u = __float_as_uint(smax[0]);
        unsigned enc = (u & 0x80000000u) ? ~u : (u | 0x80000000u);
        atomicMax(&g_maxbits, enc);
    }
}

__global__ void normalize_kernel(float* __restrict__ out) {
    int idx = blockIdx.x * 256 + threadIdx.x;
    if (idx >= TOT) return;
    unsigned u = g_maxbits;
    float mx = (u & 0x80000000u) ? __uint_as_float(u & 0x7fffffffu)
                                 : __uint_as_float(~u);
    int x = idx >> 5;
    int a = idx & 31;
    out[idx] = g_lines[a * PP + x] / mx;
}

// ---------------------------------------------------------------------------
extern "C" void kernel_launch(void* const* d_in, const int* in_sizes, int n_in,
                              void* d_out, int out_size) {
    const float* img = (const float*)d_in[0];
    float* out = (float*)d_out;

    static int s_init = 0;
    if (!s_init) {
        cudaFuncSetAttribute(gemm1_kernel,
                             cudaFuncAttributeMaxDynamicSharedMemorySize, SM_G1);
        cudaFuncSetAttribute(gemm2_kernel,
                             cudaFuncAttributeMaxDynamicSharedMemorySize, SM_G2);
        cudaFuncSetAttribute(radon_tiled_kernel,
                             cudaFuncAttributePreferredSharedMemoryCarveout, 100);
        s_init = 1;
    }

    prep_kernel<<<NBB + NCG + NTS, 256>>>(img);

    __nv_bfloat16 *pCeh, *pCel, *pCoh, *pCol;
    cudaGetSymbolAddress((void**)&pCeh, g_Ceh);
    cudaGetSymbolAddress((void**)&pCel, g_Cel);
    cudaGetSymbolAddress((void**)&pCoh, g_Coh);
    cudaGetSymbolAddress((void**)&pCol, g_Col);

    dim3 g1(HM / 128, HM / 128, 2);
    gemm1_kernel<<<g1, 256, SM_G1>>>(pCeh, pCel, pCoh, pCol);

    // gemm2: 256x128 tiles -> 8 x 8 x 2 = 128 CTAs (single wave)
    dim3 g2(HM / 128, MM / 256, 2);
    gemm2_kernel<<<g2, 256, SM_G2>>>(pCeh, pCel, pCoh, pCol);

    dim3 rg(NXT, NYT, NANG);
    radon_tiled_kernel<<<rg, 256>>>();

    reduce_max_kernel<<<(TOT + 255) / 256, 256>>>();
    normalize_kernel<<<(TOT + 255) / 256, 256>>>(out);
}